// round 2
// baseline (speedup 1.0000x reference)
#include <cuda_runtime.h>
#include <math.h>

#define NN 1024
#define BB 16
#define TT 12
#define FFD 8
#define HH 64
#define HOR 12

// ---------------- scratch buffer (no allocations allowed) ----------------
constexpr size_t SZ_XENC = (size_t)TT * NN * BB * HH;   // encoded inputs [t][n][b][h]
constexpr size_t SZ_NBH  = (size_t)NN * BB * HH;        // [n][b][64]
constexpr size_t SZ_NB2H = (size_t)NN * BB * 2 * HH;    // [n][b][128]
constexpr size_t SZ_NN2  = (size_t)NN * NN;
constexpr size_t SZ_FB   = (size_t)NN * BB * 512;

constexpr size_t OFF_XENC = 0;
constexpr size_t OFF_H    = OFF_XENC + SZ_XENC;
constexpr size_t OFF_X    = OFF_H    + SZ_NBH;
constexpr size_t OFF_S1F  = OFF_X    + SZ_NB2H;
constexpr size_t OFF_S2F  = OFF_S1F  + SZ_NB2H;
constexpr size_t OFF_S1B  = OFF_S2F  + SZ_NB2H;
constexpr size_t OFF_S2B  = OFF_S1B  + SZ_NB2H;
constexpr size_t OFF_RH   = OFF_S2B  + SZ_NB2H;
constexpr size_t OFF_U    = OFF_RH   + SZ_NBH;
constexpr size_t OFF_T1F  = OFF_U    + SZ_NBH;
constexpr size_t OFF_T2F  = OFF_T1F  + SZ_NBH;
constexpr size_t OFF_T1B  = OFF_T2F  + SZ_NBH;
constexpr size_t OFF_T2B  = OFF_T1B  + SZ_NBH;
constexpr size_t OFF_PRU  = OFF_T2B  + SZ_NBH;                 // [16384,128]
constexpr size_t OFF_PC   = OFF_PRU  + (size_t)NN * BB * 128;  // [16384,64]
constexpr size_t OFF_AF   = OFF_PC   + SZ_NBH;
constexpr size_t OFF_AB   = OFF_AF   + SZ_NN2;
constexpr size_t OFF_WF   = OFF_AB   + SZ_NN2;
constexpr size_t OFF_WB   = OFF_WF   + SZ_NN2;
constexpr size_t OFF_D1F  = OFF_WB   + SZ_NN2;
constexpr size_t OFF_D2F  = OFF_D1F  + SZ_NBH;
constexpr size_t OFF_D1B  = OFF_D2F  + SZ_NBH;
constexpr size_t OFF_D2B  = OFF_D1B  + SZ_NBH;
constexpr size_t OFF_Z    = OFF_D2B  + SZ_NBH;
constexpr size_t OFF_FB   = OFF_Z    + SZ_NBH;
constexpr size_t OFF_WRU  = OFF_FB   + SZ_FB;          // packed [512,128] = [W_r | W_u]
constexpr size_t OFF_BRU  = OFF_WRU  + (size_t)512 * 128;
constexpr size_t OFF_RS   = OFF_BRU  + 128;
constexpr size_t OFF_CS   = OFF_RS   + NN;
constexpr size_t OFF_DEGD = OFF_CS   + NN;
constexpr size_t OFF_DEGS = OFF_DEGD + NN;
constexpr size_t TOTAL_F  = OFF_DEGS + NN;

__device__ float g_buf[TOTAL_F];

// ---------------- generic tiled SGEMM ----------------
// C[M,N] (+)= A[M,K] * B[K,N], row-major with leading dims. All dims are
// multiples of the tile sizes in this problem (no edge guards needed).
template<int BM, int BN, int BK, int TM, int TN, bool ACC>
__global__ __launch_bounds__((BM / TM) * (BN / TN))
void sgemm(int M, int N, int Kd,
           const float* __restrict__ A, int lda,
           const float* __restrict__ B, int ldb,
           float* __restrict__ C, int ldc)
{
    constexpr int NT = (BM / TM) * (BN / TN);
    __shared__ float As[BK][BM];
    __shared__ float Bs[BK][BN];

    const int tid = threadIdx.x;
    const int bm  = blockIdx.y * BM;
    const int bn  = blockIdx.x * BN;
    const int tx  = tid % (BN / TN);
    const int ty  = tid / (BN / TN);

    float acc[TM][TN];
#pragma unroll
    for (int i = 0; i < TM; i++)
#pragma unroll
        for (int j = 0; j < TN; j++) acc[i][j] = 0.f;

    constexpr int A4 = BM * BK / 4;
    constexpr int B4 = BK * BN / 4;

    for (int k0 = 0; k0 < Kd; k0 += BK) {
#pragma unroll
        for (int idx = tid; idx < A4; idx += NT) {
            int row = idx / (BK / 4), c4 = idx % (BK / 4);
            float4 v = *reinterpret_cast<const float4*>(
                &A[(size_t)(bm + row) * lda + k0 + c4 * 4]);
            As[c4 * 4 + 0][row] = v.x;
            As[c4 * 4 + 1][row] = v.y;
            As[c4 * 4 + 2][row] = v.z;
            As[c4 * 4 + 3][row] = v.w;
        }
#pragma unroll
        for (int idx = tid; idx < B4; idx += NT) {
            int row = idx / (BN / 4), c4 = idx % (BN / 4);
            *reinterpret_cast<float4*>(&Bs[row][c4 * 4]) =
                *reinterpret_cast<const float4*>(
                    &B[(size_t)(k0 + row) * ldb + bn + c4 * 4]);
        }
        __syncthreads();

#pragma unroll
        for (int k = 0; k < BK; k++) {
            float af[TM], bf[TN];
#pragma unroll
            for (int i = 0; i < TM; i += 4) {
                float4 v = *reinterpret_cast<const float4*>(&As[k][ty * TM + i]);
                af[i] = v.x; af[i + 1] = v.y; af[i + 2] = v.z; af[i + 3] = v.w;
            }
#pragma unroll
            for (int j = 0; j < TN; j += 4) {
                float4 v = *reinterpret_cast<const float4*>(&Bs[k][tx * TN + j]);
                bf[j] = v.x; bf[j + 1] = v.y; bf[j + 2] = v.z; bf[j + 3] = v.w;
            }
#pragma unroll
            for (int i = 0; i < TM; i++)
#pragma unroll
                for (int j = 0; j < TN; j++)
                    acc[i][j] += af[i] * bf[j];
        }
        __syncthreads();
    }

#pragma unroll
    for (int i = 0; i < TM; i++) {
        size_t roff = (size_t)(bm + ty * TM + i) * ldc + bn + tx * TN;
#pragma unroll
        for (int j = 0; j < TN; j += 4) {
            float4 v;
            if (ACC) {
                float4 o = *reinterpret_cast<const float4*>(&C[roff + j]);
                v.x = o.x + acc[i][j];     v.y = o.y + acc[i][j + 1];
                v.z = o.z + acc[i][j + 2]; v.w = o.w + acc[i][j + 3];
            } else {
                v.x = acc[i][j];     v.y = acc[i][j + 1];
                v.z = acc[i][j + 2]; v.w = acc[i][j + 3];
            }
            *reinterpret_cast<float4*>(&C[roff + j]) = v;
        }
    }
}

// ---------------- small kernels ----------------
__global__ void k_normprep(const float* __restrict__ adj,
                           float* __restrict__ rsum, float* __restrict__ csum) {
    int i = blockIdx.x, t = threadIdx.x;
    float rs = 0.f, cs = 0.f;
    for (int j = t; j < NN; j += blockDim.x) {
        rs += adj[(size_t)i * NN + j];
        cs += adj[(size_t)j * NN + i];
    }
    __shared__ float sr[256], sc[256];
    sr[t] = rs; sc[t] = cs; __syncthreads();
    for (int s = 128; s > 0; s >>= 1) {
        if (t < s) { sr[t] += sr[t + s]; sc[t] += sc[t + s]; }
        __syncthreads();
    }
    if (t == 0) { rsum[i] = sr[0]; csum[i] = sc[0]; }
}

__global__ void k_normalize(const float* __restrict__ adj,
                            const float* __restrict__ rsum, const float* __restrict__ csum,
                            float* __restrict__ Af, float* __restrict__ Ab) {
    size_t idx = (size_t)blockIdx.x * blockDim.x + threadIdx.x;
    int i = (int)(idx / NN), j = (int)(idx % NN);
    Af[idx] = adj[idx] / rsum[i];
    Ab[idx] = adj[(size_t)j * NN + i] / csum[i];
}

__global__ void k_encoder(const float* __restrict__ x, const float* __restrict__ We,
                          const float* __restrict__ be, const float* __restrict__ emb,
                          float* __restrict__ xenc) {
    int bid = blockIdx.x;
    int b = bid % BB;
    int n = (bid / BB) % NN;
    int t = bid / (BB * NN);
    __shared__ float xv[FFD];
    int h = threadIdx.x;
    if (h < FFD) xv[h] = x[(((size_t)b * TT + t) * NN + n) * FFD + h];
    __syncthreads();
    float s = be[h] + emb[(size_t)n * HH + h];
#pragma unroll
    for (int f = 0; f < FFD; f++) s += xv[f] * We[f * HH + h];
    xenc[(((size_t)t * NN + n) * BB + b) * HH + h] = s;
}

__global__ void k_packWru(const float* __restrict__ Wr, const float* __restrict__ Wu,
                          const float* __restrict__ br, const float* __restrict__ bu,
                          float* __restrict__ Wru, float* __restrict__ bru) {
    int i = blockIdx.x * blockDim.x + threadIdx.x;
    if (i < 512 * 128) {
        int k = i >> 7, j = i & 127;
        Wru[i] = (j < 64) ? Wr[k * 64 + j] : Wu[k * 64 + (j - 64)];
    }
    if (i < 128) bru[i] = (i < 64) ? br[i] : bu[i - 64];
}

__global__ void k_buildxh(const float* __restrict__ xenc_t, const float* __restrict__ h,
                          float* __restrict__ X) {
    int i = blockIdx.x * 256 + threadIdx.x;      // NN*BB*128
    int c = i & 127, nb = i >> 7;
    X[i] = (c < 64) ? xenc_t[nb * 64 + c] : h[nb * 64 + (c - 64)];
}

__global__ void k_biasfill(float* __restrict__ C, const float* __restrict__ bias,
                           int ncols) {
    int i = blockIdx.x * 256 + threadIdx.x;
    C[i] = bias[i % ncols];
}

__global__ void k_concat_ru(float* __restrict__ FB,
                            const float* __restrict__ S1f, const float* __restrict__ S2f,
                            const float* __restrict__ S1b, const float* __restrict__ S2b) {
    int i = blockIdx.x * 256 + threadIdx.x;      // NN*BB*512
    int k = i & 511, row = i >> 9;
    int s = k >> 7, c = k & 127;
    const float* p = (s == 0) ? S1f : (s == 1) ? S2f : (s == 2) ? S1b : S2b;
    FB[i] = p[(size_t)row * 128 + c];
}

__global__ void k_gates(const float* __restrict__ Pru, const float* __restrict__ h,
                        float* __restrict__ u_out, float* __restrict__ rh) {
    int i = blockIdx.x * 256 + threadIdx.x;      // NN*BB*64
    int hh = i & 63, row = i >> 6;
    float pr = Pru[(size_t)row * 128 + hh];
    float pu = Pru[(size_t)row * 128 + 64 + hh];
    float r = 1.f / (1.f + expf(-pr));
    float u = 1.f / (1.f + expf(-pu));
    u_out[i] = u;
    rh[i] = r * h[i];
}

__global__ void k_concat_c(float* __restrict__ FB,
                           const float* __restrict__ S1f, const float* __restrict__ T1f,
                           const float* __restrict__ S2f, const float* __restrict__ T2f,
                           const float* __restrict__ S1b, const float* __restrict__ T1b,
                           const float* __restrict__ S2b, const float* __restrict__ T2b) {
    int i = blockIdx.x * 256 + threadIdx.x;      // NN*BB*512
    int k = i & 511, row = i >> 9;
    int blk = k >> 6, c = k & 63;
    const float* p; int stride;
    switch (blk) {
        case 0: p = S1f; stride = 128; break;
        case 1: p = T1f; stride = 64;  break;
        case 2: p = S2f; stride = 128; break;
        case 3: p = T2f; stride = 64;  break;
        case 4: p = S1b; stride = 128; break;
        case 5: p = T1b; stride = 64;  break;
        case 6: p = S2b; stride = 128; break;
        default: p = T2b; stride = 64; break;
    }
    FB[i] = p[(size_t)row * stride + c];
}

__global__ void k_hupdate(float* __restrict__ h, const float* __restrict__ u,
                          const float* __restrict__ Pc) {
    int i = blockIdx.x * 256 + threadIdx.x;
    float c = tanhf(Pc[i]);
    float uu = u[i];
    h[i] = uu * h[i] + (1.f - uu) * c;
}

__global__ void k_deg(const int* __restrict__ src, const int* __restrict__ dst,
                      const float* __restrict__ w,
                      float* __restrict__ degd, float* __restrict__ degs, int E) {
    int e = blockIdx.x * 256 + threadIdx.x;
    if (e < E) {
        atomicAdd(&degd[dst[e]], w[e]);
        atomicAdd(&degs[src[e]], w[e]);
    }
}

__global__ void k_buildW(const int* __restrict__ src, const int* __restrict__ dst,
                         const float* __restrict__ w,
                         const float* __restrict__ degd, const float* __restrict__ degs,
                         float* __restrict__ Wf, float* __restrict__ Wb, int E) {
    int e = blockIdx.x * 256 + threadIdx.x;
    if (e < E) {
        int s = src[e], d = dst[e];
        float we = w[e];
        float dd = degd[d];
        float ds = degs[s];
        float wf = (dd > 0.f) ? we / dd : 0.f;
        float wb = (ds > 0.f) ? we / ds : 0.f;
        atomicAdd(&Wf[(size_t)d * NN + s], wf);
        atomicAdd(&Wb[(size_t)s * NN + d], wb);
    }
}

__global__ void k_concat_d(float* __restrict__ FB,
                           const float* __restrict__ h,
                           const float* __restrict__ D1f, const float* __restrict__ D2f,
                           const float* __restrict__ D1b, const float* __restrict__ D2b) {
    int i = blockIdx.x * 256 + threadIdx.x;      // NN*BB*320
    int k = i % 320, row = i / 320;
    int blk = k / 64, c = k % 64;
    const float* p = (blk == 0) ? h : (blk == 1) ? D1f : (blk == 2) ? D2f
                   : (blk == 3) ? D1b : D2b;
    FB[i] = p[(size_t)row * 64 + c];
}

__global__ void k_decoder(const float* __restrict__ z, const float* __restrict__ Wd,
                          const float* __restrict__ bd, float* __restrict__ out) {
    int nb = blockIdx.x;                         // n*16 + b
    int n = nb >> 4, b = nb & 15;
    int j = threadIdx.x;                         // 0..95 = t*8+f
    __shared__ float zv[HH];
    if (j < HH) zv[j] = z[(size_t)nb * HH + j];
    __syncthreads();
    float s = bd[j];
#pragma unroll 8
    for (int hh = 0; hh < HH; hh++) s += zv[hh] * Wd[hh * (HOR * FFD) + j];
    int t = j >> 3, f = j & 7;
    out[(((size_t)b * HOR + t) * NN + n) * FFD + f] = s;
}

// ---------------- driver ----------------
extern "C" void kernel_launch(void* const* d_in, const int* in_sizes, int n_in,
                              void* d_out, int out_size) {
    const float* x     = (const float*)d_in[0];
    const int*   ei    = (const int*)  d_in[1];
    const float* ew    = (const float*)d_in[2];
    const float* adj   = (const float*)d_in[3];
    const float* Wenc  = (const float*)d_in[4];
    const float* benc  = (const float*)d_in[5];
    const float* nemb  = (const float*)d_in[6];
    const float* Wr    = (const float*)d_in[7];
    const float* br    = (const float*)d_in[8];
    const float* Wu    = (const float*)d_in[9];
    const float* bu    = (const float*)d_in[10];
    const float* Wc    = (const float*)d_in[11];
    const float* bc    = (const float*)d_in[12];
    const float* Wdiff = (const float*)d_in[13];
    const float* bdiff = (const float*)d_in[14];
    const float* Wdec  = (const float*)d_in[15];
    const float* bdec  = (const float*)d_in[16];
    float* out = (float*)d_out;
    const int E = in_sizes[2];
    const int* src = ei;
    const int* dst = ei + E;

    float* buf = nullptr;
    cudaGetSymbolAddress((void**)&buf, g_buf);

    float* XENC = buf + OFF_XENC;
    float* H    = buf + OFF_H;
    float* X    = buf + OFF_X;
    float* S1F  = buf + OFF_S1F;
    float* S2F  = buf + OFF_S2F;
    float* S1B  = buf + OFF_S1B;
    float* S2B  = buf + OFF_S2B;
    float* RH   = buf + OFF_RH;
    float* U    = buf + OFF_U;
    float* T1F  = buf + OFF_T1F;
    float* T2F  = buf + OFF_T2F;
    float* T1B  = buf + OFF_T1B;
    float* T2B  = buf + OFF_T2B;
    float* PRU  = buf + OFF_PRU;
    float* PC   = buf + OFF_PC;
    float* AF   = buf + OFF_AF;
    float* AB   = buf + OFF_AB;
    float* WF   = buf + OFF_WF;
    float* WB   = buf + OFF_WB;
    float* D1F  = buf + OFF_D1F;
    float* D2F  = buf + OFF_D2F;
    float* D1B  = buf + OFF_D1B;
    float* D2B  = buf + OFF_D2B;
    float* Z    = buf + OFF_Z;
    float* FB   = buf + OFF_FB;
    float* WRU  = buf + OFF_WRU;
    float* BRU  = buf + OFF_BRU;
    float* RS   = buf + OFF_RS;
    float* CS   = buf + OFF_CS;
    float* DEGD = buf + OFF_DEGD;
    float* DEGS = buf + OFF_DEGS;

    // supports + encoder + packed r/u weights
    k_normprep<<<NN, 256>>>(adj, RS, CS);
    k_normalize<<<(int)(SZ_NN2 / 256), 256>>>(adj, RS, CS, AF, AB);
    k_encoder<<<TT * NN * BB, 64>>>(x, Wenc, benc, nemb, XENC);
    k_packWru<<<(512 * 128 + 255) / 256, 256>>>(Wr, Wu, br, bu, WRU, BRU);
    cudaMemsetAsync(H, 0, SZ_NBH * sizeof(float));

    const dim3 gBig(2048 / 128, 1024 / 128);   // N=2048 hop GEMMs
    const dim3 gMid(1024 / 64, 1024 / 128);    // N=1024 hop GEMMs
    const dim3 gRu(128 / 128, 16384 / 128);    // [16384,128]+=[16384,512]@[512,128]
    const dim3 gC(64 / 64, 16384 / 128);       // [16384,64] accumulations

    for (int t = 0; t < TT; t++) {
        k_buildxh<<<(int)(SZ_NB2H / 256), 256>>>(XENC + (size_t)t * NN * BB * HH, H, X);

        sgemm<128, 128, 8, 8, 8, false><<<gBig, 256>>>(1024, 2048, 1024, AF, 1024, X,   2048, S1F, 2048);
        sgemm<128, 128, 8, 8, 8, false><<<gBig, 256>>>(1024, 2048, 1024, AF, 1024, S1F, 2048, S2F, 2048);
        sgemm<128, 128, 8, 8, 8, false><<<gBig, 256>>>(1024, 2048, 1024, AB, 1024, X,   2048, S1B, 2048);
        sgemm<128, 128, 8, 8, 8, false><<<gBig, 256>>>(1024, 2048, 1024, AB, 1024, S1B, 2048, S2B, 2048);

        k_concat_ru<<<(int)(SZ_FB / 256), 256>>>(FB, S1F, S2F, S1B, S2B);
        k_biasfill<<<(NN * BB * 128) / 256, 256>>>(PRU, BRU, 128);
        sgemm<128, 128, 8, 8, 8, true><<<gRu, 256>>>(16384, 128, 512, FB, 512, WRU, 128, PRU, 128);

        k_gates<<<(int)(SZ_NBH / 256), 256>>>(PRU, H, U, RH);

        sgemm<128, 64, 8, 8, 4, false><<<gMid, 256>>>(1024, 1024, 1024, AF, 1024, RH,  1024, T1F, 1024);
        sgemm<128, 64, 8, 8, 4, false><<<gMid, 256>>>(1024, 1024, 1024, AF, 1024, T1F, 1024, T2F, 1024);
        sgemm<128, 64, 8, 8, 4, false><<<gMid, 256>>>(1024, 1024, 1024, AB, 1024, RH,  1024, T1B, 1024);
        sgemm<128, 64, 8, 8, 4, false><<<gMid, 256>>>(1024, 1024, 1024, AB, 1024, T1B, 1024, T2B, 1024);

        k_concat_c<<<(int)(SZ_FB / 256), 256>>>(FB, S1F, T1F, S2F, T2F, S1B, T1B, S2B, T2B);
        k_biasfill<<<(int)(SZ_NBH / 256), 256>>>(PC, bc, 64);
        sgemm<128, 64, 8, 8, 4, true><<<gC, 256>>>(16384, 64, 512, FB, 512, Wc, 64, PC, 64);

        k_hupdate<<<(int)(SZ_NBH / 256), 256>>>(H, U, PC);
    }

    // ---- DiffConv readout ----
    cudaMemsetAsync(WF, 0, 2 * SZ_NN2 * sizeof(float));   // WF and WB are adjacent
    cudaMemsetAsync(DEGD, 0, 2 * NN * sizeof(float));     // DEGD and DEGS adjacent
    k_deg<<<(E + 255) / 256, 256>>>(src, dst, ew, DEGD, DEGS, E);
    k_buildW<<<(E + 255) / 256, 256>>>(src, dst, ew, DEGD, DEGS, WF, WB, E);

    sgemm<128, 64, 8, 8, 4, false><<<gMid, 256>>>(1024, 1024, 1024, WF, 1024, H,   1024, D1F, 1024);
    sgemm<128, 64, 8, 8, 4, false><<<gMid, 256>>>(1024, 1024, 1024, WF, 1024, D1F, 1024, D2F, 1024);
    sgemm<128, 64, 8, 8, 4, false><<<gMid, 256>>>(1024, 1024, 1024, WB, 1024, H,   1024, D1B, 1024);
    sgemm<128, 64, 8, 8, 4, false><<<gMid, 256>>>(1024, 1024, 1024, WB, 1024, D1B, 1024, D2B, 1024);

    k_concat_d<<<(NN * BB * 320) / 256, 256>>>(FB, H, D1F, D2F, D1B, D2B);
    k_biasfill<<<(int)(SZ_NBH / 256), 256>>>(Z, bdiff, 64);
    sgemm<128, 64, 8, 8, 4, true><<<gC, 256>>>(16384, 64, 320, FB, 320, Wdiff, 64, Z, 64);

    k_decoder<<<NN * BB, HOR * FFD>>>(Z, Wdec, bdec, out);
}

// round 10
// speedup vs baseline: 2.3899x; 2.3899x over previous
#include <cuda_runtime.h>
#include <cuda_bf16.h>
#include <math.h>
#include <stdint.h>

#define M1 (1u<<20)
constexpr size_t O_XENC=0, O_H=12*M1, O_X=13*M1, O_GK=15*M1,
 O_T1F=23*M1, O_T2F=24*M1, O_T1B=25*M1, O_T2B=26*M1, O_RH=27*M1, O_U=28*M1,
 O_PRU=29*M1, O_PC=31*M1, O_D1F=32*M1, O_D2F=33*M1, O_D1B=34*M1, O_D2B=35*M1,
 O_Z=36*M1, O_WFf=37*M1, O_EMBT=39*M1,
 O_BRU=O_EMBT+65536, O_RS=O_BRU+128, O_CS=O_RS+1024, O_DGD=O_CS+1024, O_DGS=O_DGD+1024,
 O_AFh=40*M1, O_AFl=O_AFh+M1/2, O_ABh=41*M1, O_ABl=O_ABh+M1/2,
 O_WFh=42*M1, O_WFl=43*M1,
 O_RUh=44*M1, O_RUl=O_RUh+32768, O_WCh=O_RUl+32768, O_WCl=O_WCh+32768,
 O_WDh=O_WCl+32768, O_WDl=O_WDh+20480, O_END=O_WDl+20480;
__device__ float g_buf[O_END];

// ---------- helpers ----------
__device__ __forceinline__ uint32_t s2u(const void*p){uint32_t a;asm("{ .reg .u64 t; cvta.to.shared.u64 t, %1; cvt.u32.u64 %0, t; }":"=r"(a):"l"(p));return a;}
__device__ __forceinline__ void sp(float x,__nv_bfloat16&h,__nv_bfloat16&l){h=__float2bfloat16(x);l=__float2bfloat16(x-__bfloat162float(h));}
__device__ __forceinline__ uint32_t pk(__nv_bfloat16 a,__nv_bfloat16 b){__nv_bfloat162 t;t.x=a;t.y=b;return *(uint32_t*)&t;}
__device__ __forceinline__ void ldsm4(uint32_t* r,uint32_t addr){
  asm volatile("ldmatrix.sync.aligned.m8n8.x4.shared.b16 {%0,%1,%2,%3}, [%4];"
   : "=r"(r[0]),"=r"(r[1]),"=r"(r[2]),"=r"(r[3]) : "r"(addr));
}
__device__ __forceinline__ void mmabf(float* c,const uint32_t* a,uint32_t b0,uint32_t b1){
  asm volatile("mma.sync.aligned.m16n8k16.row.col.f32.bf16.bf16.f32 "
    "{%0,%1,%2,%3}, {%4,%5,%6,%7}, {%8,%9}, {%0,%1,%2,%3};"
    : "+f"(c[0]),"+f"(c[1]),"+f"(c[2]),"+f"(c[3])
    : "r"(a[0]),"r"(a[1]),"r"(a[2]),"r"(a[3]),"r"(b0),"r"(b1));
}
// SMEM tile: 128 rows x 64 bytes (32 bf16), XOR swizzle on 16B columns
__device__ __forceinline__ uint32_t toff(int r,int kbyte){return r*64 + (kbyte ^ ((r&3)<<4));}
#define SMEMB 65536

// per-warp compute of one K=32 chunk. sbase -> [Ah 8K][Al 8K][Bh 8K][Bl 8K]
__device__ __forceinline__ void compute_chunk(uint32_t sbase,float c[2][8][4],
                                              int wm,int wn,int lane){
  const int ar=(lane&15), acs=((lane>>4)<<4);
  const int lr=lane&7, sel=lane>>3;
  const int brb=wn*64+((sel>>1)<<3)+lr, bcs=(sel&1)<<4;
#pragma unroll
  for(int s=0;s<2;s++){
    uint32_t a[2][2][4], b[4][2][4];
#pragma unroll
    for(int mt=0;mt<2;mt++){
      int r=wm*32+mt*16+ar;
      uint32_t off=toff(r,s*32+acs);
      ldsm4(a[mt][0],sbase+off);
      ldsm4(a[mt][1],sbase+8192+off);
    }
#pragma unroll
    for(int g=0;g<4;g++){
      int r=brb+g*16;
      uint32_t off=toff(r,s*32+bcs);
      ldsm4(b[g][0],sbase+16384+off);
      ldsm4(b[g][1],sbase+24576+off);
    }
#pragma unroll
    for(int mt=0;mt<2;mt++)
#pragma unroll
      for(int g=0;g<4;g++){
        mmabf(c[mt][2*g],  a[mt][0],b[g][0][0],b[g][0][1]);
        mmabf(c[mt][2*g],  a[mt][0],b[g][1][0],b[g][1][1]);
        mmabf(c[mt][2*g],  a[mt][1],b[g][0][0],b[g][0][1]);
        mmabf(c[mt][2*g+1],a[mt][0],b[g][0][2],b[g][0][3]);
        mmabf(c[mt][2*g+1],a[mt][0],b[g][1][2],b[g][1][3]);
        mmabf(c[mt][2*g+1],a[mt][1],b[g][0][2],b[g][0][3]);
      }
  }
}

// ---------- hop GEMM: C[m=chan][n=node] = sum_v A[m][v]*Adj[n][v] ----------
__global__ void __launch_bounds__(256,1) hop_mma(
    const float* A0,const float* A1,int LBa,int rbsa,
    const __nv_bfloat16* Bh0,const __nv_bfloat16* Bl0,
    const __nv_bfloat16* Bh1,const __nv_bfloat16* Bl1,
    float* C0,float* C1,int LBc,int rbsc)
{
  extern __shared__ char smem[];
  const float* A=blockIdx.z?A1:A0;
  const __nv_bfloat16* Bh=blockIdx.z?Bh1:Bh0;
  const __nv_bfloat16* Bl=blockIdx.z?Bl1:Bl0;
  float* C=blockIdx.z?C1:C0;
  const int tid=threadIdx.x, lane=tid&31, warp=tid>>5, wm=warp&3, wn=warp>>2;
  const int bm=blockIdx.y*128, bn=blockIdx.x*128;
  const int maskA=(1<<LBa)-1, maskC=(1<<LBc)-1;
  uint32_t sb=s2u(smem);

  float c[2][8][4];
#pragma unroll
  for(int i=0;i<2;i++)
#pragma unroll
    for(int j=0;j<8;j++){c[i][j][0]=0;c[i][j][1]=0;c[i][j][2]=0;c[i][j][3]=0;}

  const int r8=tid>>3, c4=tid&7;
  // chunk-0 prologue
  {
#pragma unroll
    for(int j=0;j<4;j++){
      int r=r8+j*32, gm=bm+r;
      const float* arow=A+(size_t)(gm>>LBa)*rbsa+(size_t)(gm&maskA)*1024;
      float4 v=*(const float4*)(arow+c4*4);
      __nv_bfloat16 h0,h1,h2,h3,l0,l1,l2,l3;
      sp(v.x,h0,l0);sp(v.y,h1,l1);sp(v.z,h2,l2);sp(v.w,h3,l3);
      uint32_t off=toff(r,c4*8);
      *(uint2*)(smem+off)=make_uint2(pk(h0,h1),pk(h2,h3));
      *(uint2*)(smem+8192+off)=make_uint2(pk(l0,l1),pk(l2,l3));
    }
#pragma unroll
    for(int j=0;j<4;j++){
      int idx=tid+j*256, mm=idx>>9, id2=idx&511, r=id2>>2, c16=id2&3;
      const __nv_bfloat16* src=mm?Bl:Bh;
      uint4 v=*(const uint4*)(src+(size_t)(bn+r)*1024+c16*8);
      *(uint4*)(smem+16384+mm*8192+toff(r,c16*16))=v;
    }
  }
  __syncthreads();

  for(int kc=0;kc<32;kc++){
    int cur=kc&1;
    float4 va[4]; uint4 vb[4];
    if(kc+1<32){
      int k0=(kc+1)<<5;
#pragma unroll
      for(int j=0;j<4;j++){
        int r=r8+j*32, gm=bm+r;
        const float* arow=A+(size_t)(gm>>LBa)*rbsa+(size_t)(gm&maskA)*1024;
        va[j]=*(const float4*)(arow+k0+c4*4);
      }
#pragma unroll
      for(int j=0;j<4;j++){
        int idx=tid+j*256, mm=idx>>9, id2=idx&511, r=id2>>2, c16=id2&3;
        const __nv_bfloat16* src=mm?Bl:Bh;
        vb[j]=*(const uint4*)(src+(size_t)(bn+r)*1024+k0+c16*8);
      }
    }
    compute_chunk(sb+cur*32768,c,wm,wn,lane);
    if(kc+1<32){
      char* nb=smem+(cur^1)*32768;
#pragma unroll
      for(int j=0;j<4;j++){
        int r=r8+j*32;
        __nv_bfloat16 h0,h1,h2,h3,l0,l1,l2,l3;
        sp(va[j].x,h0,l0);sp(va[j].y,h1,l1);sp(va[j].z,h2,l2);sp(va[j].w,h3,l3);
        uint32_t off=toff(r,c4*8);
        *(uint2*)(nb+off)=make_uint2(pk(h0,h1),pk(h2,h3));
        *(uint2*)(nb+8192+off)=make_uint2(pk(l0,l1),pk(l2,l3));
      }
#pragma unroll
      for(int j=0;j<4;j++){
        int idx=tid+j*256, mm=idx>>9, id2=idx&511, r=id2>>2, c16=id2&3;
        *(uint4*)(nb+16384+mm*8192+toff(r,c16*16))=vb[j];
      }
    }
    __syncthreads();
  }

  // epilogue
#pragma unroll
  for(int mt=0;mt<2;mt++){
#pragma unroll
    for(int half=0;half<2;half++){
      int gm=bm+wm*32+mt*16+(lane>>2)+half*8;
      float* crow=C+(size_t)(gm>>LBc)*rbsc+(size_t)(gm&maskC)*1024+bn+wn*64+(lane&3)*2;
#pragma unroll
      for(int f=0;f<8;f++){
        float2 v; v.x=c[mt][f][half*2]; v.y=c[mt][f][half*2+1];
        *(float2*)(crow+f*8)=v;
      }
    }
  }
}

// ---------- gate GEMM: C[b][j][v] = sum_k W^T[j][k]*Src[b][k][v] ----------
struct G8{ const float* p[8]; int bs[8]; };
__global__ void __launch_bounds__(256,1) gate_mma(
    int Ktot,int NC,int Mout,
    const __nv_bfloat16* Wh,const __nv_bfloat16* Wl,
    G8 g,const float* bias,float* C,int CbS)
{
  extern __shared__ char smem[];
  const int tid=threadIdx.x, lane=tid&31, warp=tid>>5, wm=warp&3, wn=warp>>2;
  const int bn=blockIdx.x*128, b=blockIdx.y;
  uint32_t sb=s2u(smem);

  float c[2][8][4];
#pragma unroll
  for(int i=0;i<2;i++)
#pragma unroll
    for(int j=0;j<8;j++){c[i][j][0]=0;c[i][j][1]=0;c[i][j][2]=0;c[i][j][3]=0;}

  // prologue chunk 0
  {
    const float* src=g.p[0]+(size_t)b*g.bs[0];
#pragma unroll
    for(int j=0;j<4;j++){
      int idx=tid+j*256, mm=idx>>9, id2=idx&511, r=id2>>2, c16=id2&3;
      const __nv_bfloat16* w=mm?Wl:Wh;
      uint4 v=*(const uint4*)(w+(size_t)r*Ktot+c16*8);
      *(uint4*)(smem+mm*8192+toff(r,c16*16))=v;
    }
#pragma unroll
    for(int j=0;j<4;j++){
      int idx=tid+j*256, kk=idx>>5, v4=idx&31;
      float4 v=*(const float4*)(src+(size_t)kk*1024+bn+v4*4);
      float vv[4]={v.x,v.y,v.z,v.w};
#pragma unroll
      for(int q=0;q<4;q++){
        int row=v4*4+q; __nv_bfloat16 h,l; sp(vv[q],h,l);
        uint32_t off=16384+toff(row,kk*2);
        *(__nv_bfloat16*)(smem+off)=h;
        *(__nv_bfloat16*)(smem+8192+off)=l;
      }
    }
  }
  __syncthreads();

  for(int kc=0;kc<NC;kc++){
    int cur=kc&1;
    uint4 wa[4]; float4 vb[4];
    if(kc+1<NC){
      int kn=kc+1, k0=kn<<5;
      const float* src=g.p[kn>>1]+(size_t)(kn&1)*32768+(size_t)b*g.bs[kn>>1];
#pragma unroll
      for(int j=0;j<4;j++){
        int idx=tid+j*256, mm=idx>>9, id2=idx&511, r=id2>>2, c16=id2&3;
        const __nv_bfloat16* w=mm?Wl:Wh;
        wa[j]=*(const uint4*)(w+(size_t)r*Ktot+k0+c16*8);
      }
#pragma unroll
      for(int j=0;j<4;j++){
        int idx=tid+j*256, kk=idx>>5, v4=idx&31;
        vb[j]=*(const float4*)(src+(size_t)kk*1024+bn+v4*4);
      }
    }
    compute_chunk(sb+cur*32768,c,wm,wn,lane);
    if(kc+1<NC){
      char* nb=smem+(cur^1)*32768;
#pragma unroll
      for(int j=0;j<4;j++){
        int idx=tid+j*256, mm=idx>>9, id2=idx&511, r=id2>>2, c16=id2&3;
        *(uint4*)(nb+mm*8192+toff(r,c16*16))=wa[j];
      }
#pragma unroll
      for(int j=0;j<4;j++){
        int idx=tid+j*256, kk=idx>>5, v4=idx&31;
        float vv[4]={vb[j].x,vb[j].y,vb[j].z,vb[j].w};
#pragma unroll
        for(int q=0;q<4;q++){
          int row=v4*4+q; __nv_bfloat16 h,l; sp(vv[q],h,l);
          uint32_t off=16384+toff(row,kk*2);
          *(__nv_bfloat16*)(nb+off)=h;
          *(__nv_bfloat16*)(nb+8192+off)=l;
        }
      }
    }
    __syncthreads();
  }

#pragma unroll
  for(int mt=0;mt<2;mt++){
#pragma unroll
    for(int half=0;half<2;half++){
      int m=wm*32+mt*16+(lane>>2)+half*8;
      if(m>=Mout) continue;
      float bv=bias?bias[m]:0.f;
      float* crow=C+(size_t)b*CbS+(size_t)m*1024+bn+wn*64+(lane&3)*2;
#pragma unroll
      for(int f=0;f<8;f++){
        float2 v; v.x=c[mt][f][half*2]+bv; v.y=c[mt][f][half*2+1]+bv;
        *(float2*)(crow+f*8)=v;
      }
    }
  }
}

// ---------- small kernels ----------
__global__ void k_normprep(const float* adj,float* rs,float* cs){
  int i=blockIdx.x,t=threadIdx.x; float r=0,c=0;
  for(int j=t;j<1024;j+=256){r+=adj[(size_t)i*1024+j];c+=adj[(size_t)j*1024+i];}
  __shared__ float sr[256],sc[256]; sr[t]=r;sc[t]=c;__syncthreads();
  for(int s=128;s>0;s>>=1){if(t<s){sr[t]+=sr[t+s];sc[t]+=sc[t+s];}__syncthreads();}
  if(t==0){rs[i]=sr[0];cs[i]=sc[0];}
}
__global__ void k_norm_cvt(const float* adj,const float* rs,const float* cs,
    __nv_bfloat16* AFh,__nv_bfloat16* AFl,__nv_bfloat16* ABh,__nv_bfloat16* ABl){
  size_t i=(size_t)blockIdx.x*256+threadIdx.x;
  int w=(int)(i>>10),v=(int)(i&1023);
  __nv_bfloat16 h,l;
  sp(adj[i]/rs[w],h,l); AFh[i]=h; AFl[i]=l;
  sp(adj[(size_t)v*1024+w]/cs[w],h,l); ABh[i]=h; ABl[i]=l;
}
__global__ void k_cvt(const float* s,__nv_bfloat16* h,__nv_bfloat16* l,int n){
  int i=blockIdx.x*256+threadIdx.x;
  if(i<n){__nv_bfloat16 hh,ll;sp(s[i],hh,ll);h[i]=hh;l[i]=ll;}
}
__global__ void k_embT(const float* emb,float* et){
  int i=blockIdx.x*256+threadIdx.x;
  et[i]=emb[(size_t)(i&1023)*64+(i>>10)];
}
__global__ void k_encoder(const float* x,const float* We,const float* be,
                          const float* embT,float* xenc){
  int t=blockIdx.z,b=blockIdx.y,v0=blockIdx.x*32;
  __shared__ float xv[32][8];
  int tid=threadIdx.y*32+threadIdx.x;
  xv[tid>>3][tid&7]=x[(((size_t)b*12+t)*1024+v0)*8+tid];
  __syncthreads();
  int tx=threadIdx.x;
  for(int hh=0;hh<8;hh++){
    int h=threadIdx.y*8+hh;
    float s=be[h]+embT[(size_t)h*1024+v0+tx];
#pragma unroll
    for(int f=0;f<8;f++) s+=xv[tx][f]*We[f*64+h];
    xenc[(size_t)t*M1+(size_t)(b*64+h)*1024+v0+tx]=s;
  }
}
__global__ void k_packRUT(const float* Wr,const float* Wu,const float* br,const float* bu,
    __nv_bfloat16* Wh,__nv_bfloat16* Wl,float* bru){
  int i=blockIdx.x*256+threadIdx.x;
  if(i<65536){int j=i>>9,k=i&511;
    float w=(j<64)?Wr[k*64+j]:Wu[k*64+j-64];
    __nv_bfloat16 h,l;sp(w,h,l);Wh[i]=h;Wl[i]=l;}
  if(i<128) bru[i]=(i<64)?br[i]:bu[i-64];
}
__global__ void k_packT(const float* W,__nv_bfloat16* Wh,__nv_bfloat16* Wl,int Kd){
  int i=blockIdx.x*256+threadIdx.x;
  if(i<128*Kd){int j=i/Kd,k=i-j*Kd;
    float w=(j<64)?W[k*64+j]:0.f;
    __nv_bfloat16 h,l;sp(w,h,l);Wh[i]=h;Wl[i]=l;}
}
__global__ void k_buildxh(const float* xe,const float* h,float* X){
  int i=blockIdx.x*256+threadIdx.x;
  int b=i>>17,cc=(i>>10)&127,v=i&1023;
  X[i]=(cc<64)?xe[(size_t)(b*64+cc)*1024+v]:h[(size_t)(b*64+cc-64)*1024+v];
}
__global__ void k_gates(const float* PRU,const float* H,float* U,float* RH){
  int i=blockIdx.x*256+threadIdx.x;
  int v=i&1023,j=(i>>10)&63,b=i>>16;
  float pr=PRU[(size_t)(b*128+j)*1024+v];
  float pu=PRU[(size_t)(b*128+64+j)*1024+v];
  float r=1.f/(1.f+expf(-pr)),u=1.f/(1.f+expf(-pu));
  U[i]=u; RH[i]=r*H[i];
}
__global__ void k_hupdate(float* H,const float* U,const float* PC){
  int i=blockIdx.x*256+threadIdx.x;
  float u=U[i]; H[i]=u*H[i]+(1.f-u)*tanhf(PC[i]);
}
__global__ void k_deg(const int* src,const int* dst,const float* w,
                      float* dd,float* ds,int E){
  int e=blockIdx.x*256+threadIdx.x;
  if(e<E){atomicAdd(&dd[dst[e]],w[e]);atomicAdd(&ds[src[e]],w[e]);}
}
__global__ void k_buildW(const int* src,const int* dst,const float* w,
    const float* dd,const float* ds,float* Wf,float* Wb,int E){
  int e=blockIdx.x*256+threadIdx.x;
  if(e<E){int s=src[e],d=dst[e];float we=w[e];
    float a=dd[d],b2=ds[s];
    atomicAdd(&Wf[(size_t)d*1024+s],(a>0.f)?we/a:0.f);
    atomicAdd(&Wb[(size_t)s*1024+d],(b2>0.f)?we/b2:0.f);}
}
__global__ void k_decoder(const float* Z,const float* Wd,const float* bd,float* out){
  int bn=blockIdx.x*128,b=blockIdx.y,tx=threadIdx.x;
  __shared__ float Ws[64*96],bs[96];
  for(int i=tx;i<6144;i+=128) Ws[i]=Wd[i];
  if(tx<96) bs[tx]=bd[tx];
  __syncthreads();
  int v=bn+tx;
  float z[64];
#pragma unroll
  for(int h=0;h<64;h++) z[h]=Z[(size_t)(b*64+h)*1024+v];
  for(int j=0;j<96;j++){
    float s=bs[j];
#pragma unroll
    for(int h=0;h<64;h++) s+=z[h]*Ws[h*96+j];
    out[(((size_t)b*12+(j>>3))*1024+v)*8+(j&7)]=s;
  }
}

// ---------- driver ----------
extern "C" void kernel_launch(void* const* d_in,const int* in_sizes,int n_in,
                              void* d_out,int out_size){
  const float* x=(const float*)d_in[0];
  const int* ei=(const int*)d_in[1];
  const float* ew=(const float*)d_in[2];
  const float* adj=(const float*)d_in[3];
  const float* Wenc=(const float*)d_in[4];
  const float* benc=(const float*)d_in[5];
  const float* nemb=(const float*)d_in[6];
  const float* Wr=(const float*)d_in[7];  const float* br=(const float*)d_in[8];
  const float* Wu=(const float*)d_in[9];  const float* bu=(const float*)d_in[10];
  const float* Wc=(const float*)d_in[11]; const float* bc=(const float*)d_in[12];
  const float* Wdiff=(const float*)d_in[13]; const float* bdiff=(const float*)d_in[14];
  const float* Wdec=(const float*)d_in[15];  const float* bdec=(const float*)d_in[16];
  float* out=(float*)d_out;
  const int E=in_sizes[2];
  const int* src=ei; const int* dst=ei+E;

  float* B=nullptr; cudaGetSymbolAddress((void**)&B,g_buf);
  float *XENC=B+O_XENC,*H=B+O_H,*X=B+O_X,*GK=B+O_GK,
        *T1F=B+O_T1F,*T2F=B+O_T2F,*T1B=B+O_T1B,*T2B=B+O_T2B,
        *RH=B+O_RH,*U=B+O_U,*PRU=B+O_PRU,*PC=B+O_PC,
        *D1F=B+O_D1F,*D2F=B+O_D2F,*D1B=B+O_D1B,*D2B=B+O_D2B,*Z=B+O_Z,
        *WFf=B+O_WFf,*EMBT=B+O_EMBT,*BRU=B+O_BRU,
        *RS=B+O_RS,*CS=B+O_CS,*DGD=B+O_DGD;
  __nv_bfloat16 *AFh=(__nv_bfloat16*)(B+O_AFh),*AFl=(__nv_bfloat16*)(B+O_AFl),
   *ABh=(__nv_bfloat16*)(B+O_ABh),*ABl=(__nv_bfloat16*)(B+O_ABl),
   *WFh=(__nv_bfloat16*)(B+O_WFh),*WFl=(__nv_bfloat16*)(B+O_WFl),
   *WBh=WFh+M1,*WBl=WFl+M1,
   *RUh=(__nv_bfloat16*)(B+O_RUh),*RUl=(__nv_bfloat16*)(B+O_RUl),
   *WCh=(__nv_bfloat16*)(B+O_WCh),*WCl=(__nv_bfloat16*)(B+O_WCl),
   *WDh=(__nv_bfloat16*)(B+O_WDh),*WDl=(__nv_bfloat16*)(B+O_WDl);

  cudaFuncSetAttribute(hop_mma,cudaFuncAttributeMaxDynamicSharedMemorySize,SMEMB);
  cudaFuncSetAttribute(gate_mma,cudaFuncAttributeMaxDynamicSharedMemorySize,SMEMB);

  k_normprep<<<1024,256>>>(adj,RS,CS);
  k_norm_cvt<<<4096,256>>>(adj,RS,CS,AFh,AFl,ABh,ABl);
  k_embT<<<256,256>>>(nemb,EMBT);
  k_encoder<<<dim3(32,16,12),dim3(32,8)>>>(x,Wenc,benc,EMBT,XENC);
  k_packRUT<<<256,256>>>(Wr,Wu,br,bu,RUh,RUl,BRU);
  k_packT<<<256,256>>>(Wc,WCh,WCl,512);
  k_packT<<<160,256>>>(Wdiff,WDh,WDl,320);
  cudaMemsetAsync(H,0,(size_t)M1*4);

  G8 gru, gc, gd;
  for(int i=0;i<8;i++){gru.p[i]=GK+(size_t)i*65536;gru.bs[i]=524288;}
  const float* cp[8]={GK,T1F,GK+131072,T2F,GK+262144,T1B,GK+393216,T2B};
  for(int i=0;i<8;i++){gc.p[i]=cp[i];gc.bs[i]=(i&1)?65536:524288;}
  const float* dp[8]={H,D1F,D2F,D1B,D2B,H,H,H};
  for(int i=0;i<8;i++){gd.p[i]=dp[i];gd.bs[i]=65536;}

  dim3 gBig(8,16,2), gMid(8,8,2), gGate(8,16);
  for(int t=0;t<12;t++){
    k_buildxh<<<8192,256>>>(XENC+(size_t)t*M1,H,X);
    hop_mma<<<gBig,256,SMEMB>>>(X,X,7,131072,AFh,AFl,ABh,ABl,
                                GK,GK+262144,7,524288);
    hop_mma<<<gBig,256,SMEMB>>>(GK,GK+262144,7,524288,AFh,AFl,ABh,ABl,
                                GK+131072,GK+393216,7,524288);
    gate_mma<<<gGate,256,SMEMB>>>(512,16,128,RUh,RUl,gru,BRU,PRU,131072);
    k_gates<<<4096,256>>>(PRU,H,U,RH);
    hop_mma<<<gMid,256,SMEMB>>>(RH,RH,6,65536,AFh,AFl,ABh,ABl,T1F,T1B,6,65536);
    hop_mma<<<gMid,256,SMEMB>>>(T1F,T1B,6,65536,AFh,AFl,ABh,ABl,T2F,T2B,6,65536);
    gate_mma<<<gGate,256,SMEMB>>>(512,16,64,WCh,WCl,gc,bc,PC,65536);
    k_hupdate<<<4096,256>>>(H,U,PC);
  }

  cudaMemsetAsync(WFf,0,(size_t)2*M1*4);
  cudaMemsetAsync(DGD,0,2048*4);
  k_deg<<<(E+255)/256,256>>>(src,dst,ew,DGD,DGD+1024,E);
  k_buildW<<<(E+255)/256,256>>>(src,dst,ew,DGD,DGD+1024,WFf,WFf+M1,E);
  k_cvt<<<8192,256>>>(WFf,WFh,WFl,2*M1);

  hop_mma<<<gMid,256,SMEMB>>>(H,H,6,65536,WFh,WFl,WBh,WBl,D1F,D1B,6,65536);
  hop_mma<<<gMid,256,SMEMB>>>(D1F,D1B,6,65536,WFh,WFl,WBh,WBl,D2F,D2B,6,65536);
  gate_mma<<<gGate,256,SMEMB>>>(320,10,64,WDh,WDl,gd,bdiff,Z,65536);
  k_decoder<<<dim3(8,16),128>>>(Z,Wdec,bdec,out);
}

// round 11
// speedup vs baseline: 2.4048x; 1.0063x over previous
#include <cuda_runtime.h>
#include <cuda_bf16.h>
#include <math.h>
#include <stdint.h>

#define M1 (1u<<20)
#define HK (1u<<19)
// float-unit offsets
constexpr size_t O_XEh=0, O_XEl=6*M1, O_Hf=12*M1, O_Hh=13*M1, O_Hl=13*M1+HK,
 O_GKh=14*M1, O_GKl=18*M1, O_RHh=22*M1, O_RHl=22*M1+HK, O_U=23*M1,
 O_T1Fh=24*M1, O_T1Fl=24*M1+HK, O_T2Fh=25*M1, O_T2Fl=25*M1+HK,
 O_T1Bh=26*M1, O_T1Bl=26*M1+HK, O_T2Bh=27*M1, O_T2Bl=27*M1+HK,
 O_D1Fh=28*M1, O_D1Fl=28*M1+HK, O_D2Fh=29*M1, O_D2Fl=29*M1+HK,
 O_D1Bh=30*M1, O_D1Bl=30*M1+HK, O_D2Bh=31*M1, O_D2Bl=31*M1+HK,
 O_Z=32*M1, O_WFf=33*M1,
 O_AFh=35*M1, O_AFl=35*M1+HK, O_ABh=36*M1, O_ABl=36*M1+HK,
 O_WFh=37*M1, O_WFl=38*M1, O_EMBT=39*M1,
 O_RUh=O_EMBT+65536, O_RUl=O_RUh+32768, O_WCh=O_RUl+32768, O_WCl=O_WCh+32768,
 O_WDh=O_WCl+32768, O_WDl=O_WDh+20480,
 O_BRU=O_WDl+20480, O_RS=O_BRU+128, O_CS=O_RS+1024, O_DGD=O_CS+1024,
 O_END=O_DGD+2048;
__device__ float g_buf[O_END];

// ---------- helpers ----------
__device__ __forceinline__ uint32_t s2u(const void*p){uint32_t a;asm("{ .reg .u64 t; cvta.to.shared.u64 t, %1; cvt.u32.u64 %0, t; }":"=r"(a):"l"(p));return a;}
__device__ __forceinline__ void sp(float x,__nv_bfloat16&h,__nv_bfloat16&l){h=__float2bfloat16(x);l=__float2bfloat16(x-__bfloat162float(h));}
__device__ __forceinline__ uint32_t pk(__nv_bfloat16 a,__nv_bfloat16 b){__nv_bfloat162 t;t.x=a;t.y=b;return *(uint32_t*)&t;}
__device__ __forceinline__ void ldsm4(uint32_t* r,uint32_t addr){
  asm volatile("ldmatrix.sync.aligned.m8n8.x4.shared.b16 {%0,%1,%2,%3}, [%4];"
   : "=r"(r[0]),"=r"(r[1]),"=r"(r[2]),"=r"(r[3]) : "r"(addr));
}
__device__ __forceinline__ void mmabf(float* c,const uint32_t* a,uint32_t b0,uint32_t b1){
  asm volatile("mma.sync.aligned.m16n8k16.row.col.f32.bf16.bf16.f32 "
    "{%0,%1,%2,%3}, {%4,%5,%6,%7}, {%8,%9}, {%0,%1,%2,%3};"
    : "+f"(c[0]),"+f"(c[1]),"+f"(c[2]),"+f"(c[3])
    : "r"(a[0]),"r"(a[1]),"r"(a[2]),"r"(a[3]),"r"(b0),"r"(b1));
}
__device__ __forceinline__ uint32_t toff(int r,int kbyte){return r*64 + (kbyte ^ ((r&3)<<4));}
__device__ __forceinline__ float sgm(float x){return 1.f/(1.f+expf(-x));}
#define SMEMB 65536

// per-warp compute of one K=32 chunk. buffer -> [Ah 8K][Al 8K][Bh 8K][Bl 8K]
__device__ __forceinline__ void compute_chunk(uint32_t sbase,float c[2][8][4],
                                              int wm,int wn,int lane){
  const int ar=(lane&15), acs=((lane>>4)<<4);
  const int lr=lane&7, sel=lane>>3;
  const int brb=wn*64+((sel>>1)<<3)+lr, bcs=(sel&1)<<4;
#pragma unroll
  for(int s=0;s<2;s++){
    uint32_t a[2][2][4], b[4][2][4];
#pragma unroll
    for(int mt=0;mt<2;mt++){
      int r=wm*32+mt*16+ar;
      uint32_t off=toff(r,s*32+acs);
      ldsm4(a[mt][0],sbase+off);
      ldsm4(a[mt][1],sbase+8192+off);
    }
#pragma unroll
    for(int g=0;g<4;g++){
      int r=brb+g*16;
      uint32_t off=toff(r,s*32+bcs);
      ldsm4(b[g][0],sbase+16384+off);
      ldsm4(b[g][1],sbase+24576+off);
    }
#pragma unroll
    for(int mt=0;mt<2;mt++)
#pragma unroll
      for(int g=0;g<4;g++){
        mmabf(c[mt][2*g],  a[mt][0],b[g][0][0],b[g][0][1]);
        mmabf(c[mt][2*g],  a[mt][0],b[g][1][0],b[g][1][1]);
        mmabf(c[mt][2*g],  a[mt][1],b[g][0][0],b[g][0][1]);
        mmabf(c[mt][2*g+1],a[mt][0],b[g][0][2],b[g][0][3]);
        mmabf(c[mt][2*g+1],a[mt][0],b[g][1][2],b[g][1][3]);
        mmabf(c[mt][2*g+1],a[mt][1],b[g][0][2],b[g][0][3]);
      }
  }
}

// ---------- hop GEMM: C[m=chan][n=node] = sum_v A[m][v]*Adj[n][v]; all bf16 pairs ----------
__global__ void __launch_bounds__(256,1) hop_mma(
    const __nv_bfloat16* Ah0,const __nv_bfloat16* Al0,
    const __nv_bfloat16* Ah1,const __nv_bfloat16* Al1,
    const __nv_bfloat16* A2h,const __nv_bfloat16* A2l,
    int LBa,int rbsa,
    const __nv_bfloat16* Bh0,const __nv_bfloat16* Bl0,
    const __nv_bfloat16* Bh1,const __nv_bfloat16* Bl1,
    __nv_bfloat16* Ch0,__nv_bfloat16* Cl0,
    __nv_bfloat16* Ch1,__nv_bfloat16* Cl1,
    int LBc,int rbsc)
{
  extern __shared__ char smem[];
  const __nv_bfloat16* Ah=blockIdx.z?Ah1:Ah0;
  const __nv_bfloat16* Al=blockIdx.z?Al1:Al0;
  const __nv_bfloat16* Bh=blockIdx.z?Bh1:Bh0;
  const __nv_bfloat16* Bl=blockIdx.z?Bl1:Bl0;
  __nv_bfloat16* Ch=blockIdx.z?Ch1:Ch0;
  __nv_bfloat16* Cl=blockIdx.z?Cl1:Cl0;
  const int tid=threadIdx.x, lane=tid&31, warp=tid>>5, wm=warp&3, wn=warp>>2;
  const int bm=blockIdx.y*128, bn=blockIdx.x*128;
  uint32_t sb=s2u(smem);

  float c[2][8][4];
#pragma unroll
  for(int i=0;i<2;i++)
#pragma unroll
    for(int j=0;j<8;j++){c[i][j][0]=0;c[i][j][1]=0;c[i][j][2]=0;c[i][j][3]=0;}

  // per-thread fixed pointers/offsets
  const __nv_bfloat16* aptr[4]; uint32_t soA[4];
  const __nv_bfloat16* bptr[4]; uint32_t soB[4];
#pragma unroll
  for(int j=0;j<4;j++){
    int idx=tid+j*256, mm=idx>>9, id2=idx&511, r=id2>>2, c16=id2&3;
    int gm=bm+r;
    const __nv_bfloat16 *ph,*pl; size_t addr;
    if(A2h){
      int cc=gm&127;
      if(cc&64){ph=A2h;pl=A2l;} else {ph=Ah;pl=Al;}
      addr=(size_t)(gm>>7)*65536+(size_t)(cc&63)*1024;
    } else {
      ph=Ah; pl=Al;
      addr=(size_t)(gm>>LBa)*rbsa+(size_t)(gm&((1<<LBa)-1))*1024;
    }
    aptr[j]=(mm?pl:ph)+addr+c16*8;
    soA[j]=mm*8192+toff(r,c16*16);
    bptr[j]=(mm?Bl:Bh)+(size_t)(bn+r)*1024+c16*8;
    soB[j]=16384+mm*8192+toff(r,c16*16);
  }
  // prologue chunk 0
#pragma unroll
  for(int j=0;j<4;j++){
    *(uint4*)(smem+soA[j])=*(const uint4*)(aptr[j]);
    *(uint4*)(smem+soB[j])=*(const uint4*)(bptr[j]);
  }
  __syncthreads();

  for(int kc=0;kc<32;kc++){
    int cur=kc&1;
    uint4 ua[4],ub[4];
    if(kc<31){
      int k0=(kc+1)<<5;
#pragma unroll
      for(int j=0;j<4;j++){
        ua[j]=*(const uint4*)(aptr[j]+k0);
        ub[j]=*(const uint4*)(bptr[j]+k0);
      }
    }
    compute_chunk(sb+cur*32768,c,wm,wn,lane);
    if(kc<31){
      char* nb=smem+(cur^1)*32768;
#pragma unroll
      for(int j=0;j<4;j++){
        *(uint4*)(nb+soA[j])=ua[j];
        *(uint4*)(nb+soB[j])=ub[j];
      }
    }
    __syncthreads();
  }

  // epilogue: write bf16 pair
#pragma unroll
  for(int mt=0;mt<2;mt++){
#pragma unroll
    for(int half=0;half<2;half++){
      int gm=bm+wm*32+mt*16+(lane>>2)+half*8;
      size_t rowoff=(size_t)(gm>>LBc)*rbsc+(size_t)(gm&((1<<LBc)-1))*1024
                   +bn+wn*64+(lane&3)*2;
#pragma unroll
      for(int f=0;f<8;f++){
        float v0=c[mt][f][half*2], v1=c[mt][f][half*2+1];
        __nv_bfloat16 h0,l0,h1,l1; sp(v0,h0,l0); sp(v1,h1,l1);
        *(uint32_t*)(Ch+rowoff+f*8)=pk(h0,h1);
        *(uint32_t*)(Cl+rowoff+f*8)=pk(l0,l1);
      }
    }
  }
}

// ---------- gate GEMM with fused epilogues ----------
struct G8P{ const __nv_bfloat16* h[8]; const __nv_bfloat16* l[8]; int bs[8]; };
// mode 0: r/u gates -> RH pair (m<64), U fp32 (m>=64)
// mode 1: c gate    -> H update (fp32 + pair)
// mode 2: diff      -> Z fp32
__global__ void __launch_bounds__(256,1) gate_mma(
    int Ktot,int NC,int mode,
    const __nv_bfloat16* Wh,const __nv_bfloat16* Wl,
    G8P g,const float* bias,
    float* Hf,float* U,
    __nv_bfloat16* RHh,__nv_bfloat16* RHl,
    __nv_bfloat16* Hh,__nv_bfloat16* Hl,
    float* Z)
{
  extern __shared__ char smem[];
  const int tid=threadIdx.x, lane=tid&31, warp=tid>>5, wm=warp&3, wn=warp>>2;
  const int bn=blockIdx.x*128, b=blockIdx.y;
  uint32_t sb=s2u(smem);

  float c[2][8][4];
#pragma unroll
  for(int i=0;i<2;i++)
#pragma unroll
    for(int j=0;j<8;j++){c[i][j][0]=0;c[i][j][1]=0;c[i][j][2]=0;c[i][j][3]=0;}

  const __nv_bfloat16* wptr[4]; uint32_t soW[4];
#pragma unroll
  for(int j=0;j<4;j++){
    int idx=tid+j*256, mm=idx>>9, id2=idx&511, r=id2>>2, c16=id2&3;
    wptr[j]=(mm?Wl:Wh)+(size_t)r*Ktot+c16*8;
    soW[j]=mm*8192+toff(r,c16*16);
  }
  // prologue chunk 0
  {
    const __nv_bfloat16* srch=g.h[0]+(size_t)b*g.bs[0];
    const __nv_bfloat16* srcl=g.l[0]+(size_t)b*g.bs[0];
#pragma unroll
    for(int j=0;j<4;j++)
      *(uint4*)(smem+soW[j])=*(const uint4*)(wptr[j]);
#pragma unroll
    for(int j=0;j<4;j++){
      int idx=tid+j*256, kk=idx>>5, v4=idx&31;
      uint2 vh=*(const uint2*)(srch+(size_t)kk*1024+bn+v4*4);
      uint2 vl=*(const uint2*)(srcl+(size_t)kk*1024+bn+v4*4);
      int r0=v4*4;
      *(uint16_t*)(smem+16384+toff(r0  ,kk*2))=(uint16_t)(vh.x);
      *(uint16_t*)(smem+16384+toff(r0+1,kk*2))=(uint16_t)(vh.x>>16);
      *(uint16_t*)(smem+16384+toff(r0+2,kk*2))=(uint16_t)(vh.y);
      *(uint16_t*)(smem+16384+toff(r0+3,kk*2))=(uint16_t)(vh.y>>16);
      *(uint16_t*)(smem+24576+toff(r0  ,kk*2))=(uint16_t)(vl.x);
      *(uint16_t*)(smem+24576+toff(r0+1,kk*2))=(uint16_t)(vl.x>>16);
      *(uint16_t*)(smem+24576+toff(r0+2,kk*2))=(uint16_t)(vl.y);
      *(uint16_t*)(smem+24576+toff(r0+3,kk*2))=(uint16_t)(vl.y>>16);
    }
  }
  __syncthreads();

  for(int kc=0;kc<NC;kc++){
    int cur=kc&1;
    uint4 uw[4]; uint2 vh[4],vl[4];
    if(kc+1<NC){
      int kn=kc+1, k0=kn<<5;
      const __nv_bfloat16* srch=g.h[kn>>1]+(size_t)(kn&1)*32768+(size_t)b*g.bs[kn>>1];
      const __nv_bfloat16* srcl=g.l[kn>>1]+(size_t)(kn&1)*32768+(size_t)b*g.bs[kn>>1];
#pragma unroll
      for(int j=0;j<4;j++) uw[j]=*(const uint4*)(wptr[j]+k0);
#pragma unroll
      for(int j=0;j<4;j++){
        int idx=tid+j*256, kk=idx>>5, v4=idx&31;
        vh[j]=*(const uint2*)(srch+(size_t)kk*1024+bn+v4*4);
        vl[j]=*(const uint2*)(srcl+(size_t)kk*1024+bn+v4*4);
      }
    }
    compute_chunk(sb+cur*32768,c,wm,wn,lane);
    if(kc+1<NC){
      char* nb=smem+(cur^1)*32768;
#pragma unroll
      for(int j=0;j<4;j++)
        *(uint4*)(nb+soW[j])=uw[j];
#pragma unroll
      for(int j=0;j<4;j++){
        int idx=tid+j*256, kk=idx>>5, v4=idx&31;
        int r0=v4*4;
        *(uint16_t*)(nb+16384+toff(r0  ,kk*2))=(uint16_t)(vh[j].x);
        *(uint16_t*)(nb+16384+toff(r0+1,kk*2))=(uint16_t)(vh[j].x>>16);
        *(uint16_t*)(nb+16384+toff(r0+2,kk*2))=(uint16_t)(vh[j].y);
        *(uint16_t*)(nb+16384+toff(r0+3,kk*2))=(uint16_t)(vh[j].y>>16);
        *(uint16_t*)(nb+24576+toff(r0  ,kk*2))=(uint16_t)(vl[j].x);
        *(uint16_t*)(nb+24576+toff(r0+1,kk*2))=(uint16_t)(vl[j].x>>16);
        *(uint16_t*)(nb+24576+toff(r0+2,kk*2))=(uint16_t)(vl[j].y);
        *(uint16_t*)(nb+24576+toff(r0+3,kk*2))=(uint16_t)(vl[j].y>>16);
      }
    }
    __syncthreads();
  }

  // fused epilogues
#pragma unroll
  for(int mt=0;mt<2;mt++){
#pragma unroll
    for(int half=0;half<2;half++){
      int m=wm*32+mt*16+(lane>>2)+half*8;
      int col=bn+wn*64+(lane&3)*2;
      if(mode==0){
        float bv=bias[m];
        if(m<64){
          size_t ro=(size_t)(b*64+m)*1024+col;
#pragma unroll
          for(int f=0;f<8;f++){
            float2 hv=*(const float2*)(Hf+ro+f*8);
            float r0=sgm(c[mt][f][half*2]+bv), r1=sgm(c[mt][f][half*2+1]+bv);
            float x0=r0*hv.x, x1=r1*hv.y;
            __nv_bfloat16 h0,l0,h1,l1; sp(x0,h0,l0); sp(x1,h1,l1);
            *(uint32_t*)(RHh+ro+f*8)=pk(h0,h1);
            *(uint32_t*)(RHl+ro+f*8)=pk(l0,l1);
          }
        } else {
          size_t ro=(size_t)(b*64+(m-64))*1024+col;
#pragma unroll
          for(int f=0;f<8;f++){
            float2 v; v.x=sgm(c[mt][f][half*2]+bv); v.y=sgm(c[mt][f][half*2+1]+bv);
            *(float2*)(U+ro+f*8)=v;
          }
        }
      } else if(mode==1){
        if(m<64){
          float bv=bias[m];
          size_t ro=(size_t)(b*64+m)*1024+col;
#pragma unroll
          for(int f=0;f<8;f++){
            float2 uu=*(const float2*)(U+ro+f*8);
            float2 hh=*(const float2*)(Hf+ro+f*8);
            float c0=tanhf(c[mt][f][half*2]+bv), c1=tanhf(c[mt][f][half*2+1]+bv);
            float n0=uu.x*hh.x+(1.f-uu.x)*c0;
            float n1=uu.y*hh.y+(1.f-uu.y)*c1;
            float2 v; v.x=n0; v.y=n1;
            *(float2*)(Hf+ro+f*8)=v;
            __nv_bfloat16 h0,l0,h1,l1; sp(n0,h0,l0); sp(n1,h1,l1);
            *(uint32_t*)(Hh+ro+f*8)=pk(h0,h1);
            *(uint32_t*)(Hl+ro+f*8)=pk(l0,l1);
          }
        }
      } else {
        if(m<64){
          float bv=bias[m];
          size_t ro=(size_t)(b*64+m)*1024+col;
#pragma unroll
          for(int f=0;f<8;f++){
            float2 v; v.x=c[mt][f][half*2]+bv; v.y=c[mt][f][half*2+1]+bv;
            *(float2*)(Z+ro+f*8)=v;
          }
        }
      }
    }
  }
}

// ---------- small kernels ----------
__global__ void k_normprep(const float* adj,float* rs,float* cs){
  int i=blockIdx.x,t=threadIdx.x; float r=0,c=0;
  for(int j=t;j<1024;j+=256){r+=adj[(size_t)i*1024+j];c+=adj[(size_t)j*1024+i];}
  __shared__ float sr[256],sc[256]; sr[t]=r;sc[t]=c;__syncthreads();
  for(int s=128;s>0;s>>=1){if(t<s){sr[t]+=sr[t+s];sc[t]+=sc[t+s];}__syncthreads();}
  if(t==0){rs[i]=sr[0];cs[i]=sc[0];}
}
__global__ void k_norm_cvt(const float* adj,const float* rs,const float* cs,
    __nv_bfloat16* AFh,__nv_bfloat16* AFl,__nv_bfloat16* ABh,__nv_bfloat16* ABl){
  size_t i=(size_t)blockIdx.x*256+threadIdx.x;
  int w=(int)(i>>10),v=(int)(i&1023);
  __nv_bfloat16 h,l;
  sp(adj[i]/rs[w],h,l); AFh[i]=h; AFl[i]=l;
  sp(adj[(size_t)v*1024+w]/cs[w],h,l); ABh[i]=h; ABl[i]=l;
}
__global__ void k_cvt(const float* s,__nv_bfloat16* h,__nv_bfloat16* l,int n){
  int i=blockIdx.x*256+threadIdx.x;
  if(i<n){__nv_bfloat16 hh,ll;sp(s[i],hh,ll);h[i]=hh;l[i]=ll;}
}
__global__ void k_embT(const float* emb,float* et){
  int i=blockIdx.x*256+threadIdx.x;
  et[i]=emb[(size_t)(i&1023)*64+(i>>10)];
}
__global__ void k_encoder(const float* x,const float* We,const float* be,
                          const float* embT,__nv_bfloat16* XEh,__nv_bfloat16* XEl){
  int t=blockIdx.z,b=blockIdx.y,v0=blockIdx.x*32;
  __shared__ float xv[32][8];
  int tid=threadIdx.y*32+threadIdx.x;
  xv[tid>>3][tid&7]=x[(((size_t)b*12+t)*1024+v0)*8+tid];
  __syncthreads();
  int tx=threadIdx.x;
  for(int hh=0;hh<8;hh++){
    int h=threadIdx.y*8+hh;
    float s=be[h]+embT[(size_t)h*1024+v0+tx];
#pragma unroll
    for(int f=0;f<8;f++) s+=xv[tx][f]*We[f*64+h];
    __nv_bfloat16 bh,bl; sp(s,bh,bl);
    size_t o=(size_t)t*M1+(size_t)(b*64+h)*1024+v0+tx;
    XEh[o]=bh; XEl[o]=bl;
  }
}
__global__ void k_packRUT(const float* Wr,const float* Wu,const float* br,const float* bu,
    __nv_bfloat16* Wh,__nv_bfloat16* Wl,float* bru){
  int i=blockIdx.x*256+threadIdx.x;
  if(i<65536){int j=i>>9,k=i&511;
    float w=(j<64)?Wr[k*64+j]:Wu[k*64+j-64];
    __nv_bfloat16 h,l;sp(w,h,l);Wh[i]=h;Wl[i]=l;}
  if(i<128) bru[i]=(i<64)?br[i]:bu[i-64];
}
__global__ void k_packT(const float* W,__nv_bfloat16* Wh,__nv_bfloat16* Wl,int Kd){
  int i=blockIdx.x*256+threadIdx.x;
  if(i<128*Kd){int j=i/Kd,k=i-j*Kd;
    float w=(j<64)?W[k*64+j]:0.f;
    __nv_bfloat16 h,l;sp(w,h,l);Wh[i]=h;Wl[i]=l;}
}
__global__ void k_deg(const int* src,const int* dst,const float* w,
                      float* dd,float* ds,int E){
  int e=blockIdx.x*256+threadIdx.x;
  if(e<E){atomicAdd(&dd[dst[e]],w[e]);atomicAdd(&ds[src[e]],w[e]);}
}
__global__ void k_buildW(const int* src,const int* dst,const float* w,
    const float* dd,const float* ds,float* Wf,float* Wb,int E){
  int e=blockIdx.x*256+threadIdx.x;
  if(e<E){int s=src[e],d=dst[e];float we=w[e];
    float a=dd[d],b2=ds[s];
    atomicAdd(&Wf[(size_t)d*1024+s],(a>0.f)?we/a:0.f);
    atomicAdd(&Wb[(size_t)s*1024+d],(b2>0.f)?we/b2:0.f);}
}
__global__ void k_decoder(const float* Z,const float* Wd,const float* bd,float* out){
  int bn=blockIdx.x*128,b=blockIdx.y,tx=threadIdx.x;
  __shared__ float Ws[64*96],bs[96];
  for(int i=tx;i<6144;i+=128) Ws[i]=Wd[i];
  if(tx<96) bs[tx]=bd[tx];
  __syncthreads();
  int v=bn+tx;
  float z[64];
#pragma unroll
  for(int h=0;h<64;h++) z[h]=Z[(size_t)(b*64+h)*1024+v];
  for(int j=0;j<96;j++){
    float s=bs[j];
#pragma unroll
    for(int h=0;h<64;h++) s+=z[h]*Ws[h*96+j];
    out[(((size_t)b*12+(j>>3))*1024+v)*8+(j&7)]=s;
  }
}

// ---------- driver ----------
extern "C" void kernel_launch(void* const* d_in,const int* in_sizes,int n_in,
                              void* d_out,int out_size){
  const float* x=(const float*)d_in[0];
  const int* ei=(const int*)d_in[1];
  const float* ew=(const float*)d_in[2];
  const float* adj=(const float*)d_in[3];
  const float* Wenc=(const float*)d_in[4];
  const float* benc=(const float*)d_in[5];
  const float* nemb=(const float*)d_in[6];
  const float* Wr=(const float*)d_in[7];  const float* br=(const float*)d_in[8];
  const float* Wu=(const float*)d_in[9];  const float* bu=(const float*)d_in[10];
  const float* Wc=(const float*)d_in[11]; const float* bc=(const float*)d_in[12];
  const float* Wdiff=(const float*)d_in[13]; const float* bdiff=(const float*)d_in[14];
  const float* Wdec=(const float*)d_in[15];  const float* bdec=(const float*)d_in[16];
  float* out=(float*)d_out;
  const int E=in_sizes[2];
  const int* src=ei; const int* dst=ei+E;

  float* B=nullptr; cudaGetSymbolAddress((void**)&B,g_buf);
  float *Hf=B+O_Hf,*U=B+O_U,*Z=B+O_Z,*WFf=B+O_WFf,*EMBT=B+O_EMBT,
        *BRU=B+O_BRU,*RS=B+O_RS,*CS=B+O_CS,*DGD=B+O_DGD;
#define BP(o) ((__nv_bfloat16*)(B+(o)))
  __nv_bfloat16 *XEh=BP(O_XEh),*XEl=BP(O_XEl),*Hh=BP(O_Hh),*Hl=BP(O_Hl),
   *GKh=BP(O_GKh),*GKl=BP(O_GKl),*RHh=BP(O_RHh),*RHl=BP(O_RHl),
   *T1Fh=BP(O_T1Fh),*T1Fl=BP(O_T1Fl),*T2Fh=BP(O_T2Fh),*T2Fl=BP(O_T2Fl),
   *T1Bh=BP(O_T1Bh),*T1Bl=BP(O_T1Bl),*T2Bh=BP(O_T2Bh),*T2Bl=BP(O_T2Bl),
   *D1Fh=BP(O_D1Fh),*D1Fl=BP(O_D1Fl),*D2Fh=BP(O_D2Fh),*D2Fl=BP(O_D2Fl),
   *D1Bh=BP(O_D1Bh),*D1Bl=BP(O_D1Bl),*D2Bh=BP(O_D2Bh),*D2Bl=BP(O_D2Bl),
   *AFh=BP(O_AFh),*AFl=BP(O_AFl),*ABh=BP(O_ABh),*ABl=BP(O_ABl),
   *WFh=BP(O_WFh),*WFl=BP(O_WFl),*WBh=BP(O_WFh)+M1,*WBl=BP(O_WFl)+M1,
   *RUh=BP(O_RUh),*RUl=BP(O_RUl),*WCh=BP(O_WCh),*WCl=BP(O_WCl),
   *WDh=BP(O_WDh),*WDl=BP(O_WDl);

  cudaFuncSetAttribute(hop_mma,cudaFuncAttributeMaxDynamicSharedMemorySize,SMEMB);
  cudaFuncSetAttribute(gate_mma,cudaFuncAttributeMaxDynamicSharedMemorySize,SMEMB);

  k_normprep<<<1024,256>>>(adj,RS,CS);
  k_norm_cvt<<<4096,256>>>(adj,RS,CS,AFh,AFl,ABh,ABl);
  k_embT<<<256,256>>>(nemb,EMBT);
  k_encoder<<<dim3(32,16,12),dim3(32,8)>>>(x,Wenc,benc,EMBT,XEh,XEl);
  k_packRUT<<<256,256>>>(Wr,Wu,br,bu,RUh,RUl,BRU);
  k_packT<<<256,256>>>(Wc,WCh,WCl,512);
  k_packT<<<160,256>>>(Wdiff,WDh,WDl,320);
  cudaMemsetAsync(Hf,0,(size_t)2*M1*4);   // Hf (1M f32) + Hh/Hl (2M bf16)

  G8P gru,gc,gd;
  for(int i=0;i<8;i++){
    gru.h[i]=GKh+(size_t)i*65536; gru.l[i]=GKl+(size_t)i*65536; gru.bs[i]=524288;
  }
  {
    const __nv_bfloat16* ch[8]={GKh,T1Fh,GKh+131072,T2Fh,GKh+262144,T1Bh,GKh+393216,T2Bh};
    const __nv_bfloat16* cl[8]={GKl,T1Fl,GKl+131072,T2Fl,GKl+262144,T1Bl,GKl+393216,T2Bl};
    for(int i=0;i<8;i++){gc.h[i]=ch[i];gc.l[i]=cl[i];gc.bs[i]=(i&1)?65536:524288;}
  }
  {
    const __nv_bfloat16* dh[8]={Hh,D1Fh,D2Fh,D1Bh,D2Bh,Hh,Hh,Hh};
    const __nv_bfloat16* dl[8]={Hl,D1Fl,D2Fl,D1Bl,D2Bl,Hl,Hl,Hl};
    for(int i=0;i<8;i++){gd.h[i]=dh[i];gd.l[i]=dl[i];gd.bs[i]=65536;}
  }

  dim3 gBig(8,16,2), gMid(8,8,2), gGate(8,16);
  for(int t=0;t<12;t++){
    const __nv_bfloat16* xth=XEh+(size_t)t*M1;
    const __nv_bfloat16* xtl=XEl+(size_t)t*M1;
    // S1: hops of [xt,h] -> GK slabs (rows: S1F@0, S1B@256 of each 512-row slab)
    hop_mma<<<gBig,256,SMEMB>>>(xth,xtl,xth,xtl,Hh,Hl,7,65536,
                                AFh,AFl,ABh,ABl,
                                GKh,GKl,GKh+262144,GKl+262144,7,524288);
    // S2: hops of S1 -> S2F@128, S2B@384
    hop_mma<<<gBig,256,SMEMB>>>(GKh,GKl,GKh+262144,GKl+262144,nullptr,nullptr,7,524288,
                                AFh,AFl,ABh,ABl,
                                GKh+131072,GKl+131072,GKh+393216,GKl+393216,7,524288);
    // r/u gates fused: RH pair + U
    gate_mma<<<gGate,256,SMEMB>>>(512,16,0,RUh,RUl,gru,BRU,
                                  Hf,U,RHh,RHl,Hh,Hl,Z);
    // T1, T2 hops of RH
    hop_mma<<<gMid,256,SMEMB>>>(RHh,RHl,RHh,RHl,nullptr,nullptr,6,65536,
                                AFh,AFl,ABh,ABl,
                                T1Fh,T1Fl,T1Bh,T1Bl,6,65536);
    hop_mma<<<gMid,256,SMEMB>>>(T1Fh,T1Fl,T1Bh,T1Bl,nullptr,nullptr,6,65536,
                                AFh,AFl,ABh,ABl,
                                T2Fh,T2Fl,T2Bh,T2Bl,6,65536);
    // c gate fused: H update (fp32 + pair)
    gate_mma<<<gGate,256,SMEMB>>>(512,16,1,WCh,WCl,gc,bc,
                                  Hf,U,RHh,RHl,Hh,Hl,Z);
  }

  // ---- DiffConv readout ----
  cudaMemsetAsync(WFf,0,(size_t)2*M1*4);
  cudaMemsetAsync(DGD,0,2048*4);
  k_deg<<<(E+255)/256,256>>>(src,dst,ew,DGD,DGD+1024,E);
  k_buildW<<<(E+255)/256,256>>>(src,dst,ew,DGD,DGD+1024,WFf,WFf+M1,E);
  k_cvt<<<8192,256>>>(WFf,WFh,WFl,2*M1);

  hop_mma<<<gMid,256,SMEMB>>>(Hh,Hl,Hh,Hl,nullptr,nullptr,6,65536,
                              WFh,WFl,WBh,WBl,
                              D1Fh,D1Fl,D1Bh,D1Bl,6,65536);
  hop_mma<<<gMid,256,SMEMB>>>(D1Fh,D1Fl,D1Bh,D1Bl,nullptr,nullptr,6,65536,
                              WFh,WFl,WBh,WBl,
                              D2Fh,D2Fl,D2Bh,D2Bl,6,65536);
  gate_mma<<<gGate,256,SMEMB>>>(320,10,2,WDh,WDl,gd,bdiff,
                                Hf,U,RHh,RHl,Hh,Hl,Z);
  k_decoder<<<dim3(8,16),128>>>(Z,Wdec,bdec,out);
}

// round 12
// speedup vs baseline: 2.4262x; 1.0089x over previous
#include <cuda_runtime.h>
#include <cuda_bf16.h>
#include <math.h>
#include <stdint.h>

#define M1 ((size_t)1<<20)
#define HK ((size_t)1<<19)
// float-unit offsets
constexpr size_t O_XEh=0, O_XEl=6*M1,
 O_XHh=12*M1, O_XHl=36*M1,            // per support s: +s*6*M1, per t: +t*HK
 O_HHh=60*M1, O_HHl=62*M1,            // per s: +s*HK
 O_THh=64*M1, O_THl=66*M1,
 O_Hf=68*M1, O_Hh=69*M1, O_Hl=69*M1+HK,
 O_RHh=70*M1, O_RHl=70*M1+HK,
 O_U=71*M1, O_Z=72*M1,
 O_D1Fh=73*M1, O_D1Fl=73*M1+HK, O_D1Bh=74*M1, O_D1Bl=74*M1+HK,
 O_D2Fh=75*M1, O_D2Fl=75*M1+HK, O_D2Bh=76*M1, O_D2Bl=76*M1+HK,
 O_WFf=77*M1,
 O_AFh=79*M1, O_AFl=79*M1+HK, O_A2Fh=80*M1, O_A2Fl=80*M1+HK,
 O_ABh=81*M1, O_ABl=81*M1+HK, O_A2Bh=82*M1, O_A2Bl=82*M1+HK,
 O_AFth=83*M1, O_AFtl=83*M1+HK, O_ABth=84*M1, O_ABtl=84*M1+HK,
 O_WFh=85*M1, O_WFl=85*M1+HK, O_WBh=86*M1, O_WBl=86*M1+HK,
 O_EMBT=87*M1,
 O_RUh=O_EMBT+65536, O_RUl=O_RUh+32768,
 O_WCh=O_RUl+32768, O_WCl=O_WCh+32768,
 O_WDh=O_WCl+32768, O_WDl=O_WDh+20480,
 O_BRU=O_WDl+20480, O_RS=O_BRU+128, O_CS=O_RS+1024, O_DGD=O_CS+1024,
 O_END=O_DGD+2048;
__device__ float g_buf[O_END];

// ---------- helpers ----------
__device__ __forceinline__ uint32_t s2u(const void*p){uint32_t a;asm("{ .reg .u64 t; cvta.to.shared.u64 t, %1; cvt.u32.u64 %0, t; }":"=r"(a):"l"(p));return a;}
__device__ __forceinline__ void sp(float x,__nv_bfloat16&h,__nv_bfloat16&l){h=__float2bfloat16(x);l=__float2bfloat16(x-__bfloat162float(h));}
__device__ __forceinline__ uint32_t pk(__nv_bfloat16 a,__nv_bfloat16 b){__nv_bfloat162 t;t.x=a;t.y=b;return *(uint32_t*)&t;}
__device__ __forceinline__ void ldsm4(uint32_t* r,uint32_t addr){
  asm volatile("ldmatrix.sync.aligned.m8n8.x4.shared.b16 {%0,%1,%2,%3}, [%4];"
   : "=r"(r[0]),"=r"(r[1]),"=r"(r[2]),"=r"(r[3]) : "r"(addr));
}
__device__ __forceinline__ void mmabf(float* c,const uint32_t* a,uint32_t b0,uint32_t b1){
  asm volatile("mma.sync.aligned.m16n8k16.row.col.f32.bf16.bf16.f32 "
    "{%0,%1,%2,%3}, {%4,%5,%6,%7}, {%8,%9}, {%0,%1,%2,%3};"
    : "+f"(c[0]),"+f"(c[1]),"+f"(c[2]),"+f"(c[3])
    : "r"(a[0]),"r"(a[1]),"r"(a[2]),"r"(a[3]),"r"(b0),"r"(b1));
}
__device__ __forceinline__ uint32_t toff(int r,int kbyte){return r*64 + (kbyte ^ ((r&3)<<4));}
__device__ __forceinline__ float sgm(float x){return 1.f/(1.f+expf(-x));}
#define SMEMB 65536

__device__ __forceinline__ void compute_chunk(uint32_t sbase,float c[2][8][4],
                                              int wm,int wn,int lane){
  const int ar=(lane&15), acs=((lane>>4)<<4);
  const int lr=lane&7, sel=lane>>3;
  const int brb=wn*64+((sel>>1)<<3)+lr, bcs=(sel&1)<<4;
#pragma unroll
  for(int s=0;s<2;s++){
    uint32_t a[2][2][4], b[4][2][4];
#pragma unroll
    for(int mt=0;mt<2;mt++){
      int r=wm*32+mt*16+ar;
      uint32_t off=toff(r,s*32+acs);
      ldsm4(a[mt][0],sbase+off);
      ldsm4(a[mt][1],sbase+8192+off);
    }
#pragma unroll
    for(int g=0;g<4;g++){
      int r=brb+g*16;
      uint32_t off=toff(r,s*32+bcs);
      ldsm4(b[g][0],sbase+16384+off);
      ldsm4(b[g][1],sbase+24576+off);
    }
#pragma unroll
    for(int mt=0;mt<2;mt++)
#pragma unroll
      for(int g=0;g<4;g++){
        mmabf(c[mt][2*g],  a[mt][0],b[g][0][0],b[g][0][1]);
        mmabf(c[mt][2*g],  a[mt][0],b[g][1][0],b[g][1][1]);
        mmabf(c[mt][2*g],  a[mt][1],b[g][0][0],b[g][0][1]);
        mmabf(c[mt][2*g+1],a[mt][0],b[g][0][2],b[g][0][3]);
        mmabf(c[mt][2*g+1],a[mt][0],b[g][1][2],b[g][1][3]);
        mmabf(c[mt][2*g+1],a[mt][1],b[g][0][2],b[g][0][3]);
      }
  }
}

// ---------- hop GEMM: C[m][n] = sum_v A[m][v]*B[n][v]; per-z operand sets ----------
struct Z4 {
  const __nv_bfloat16 *Ah[4],*Al[4],*Bh[4],*Bl[4];
  __nv_bfloat16 *Ch[4],*Cl[4];
};
__global__ void __launch_bounds__(256,1) hop_mma(Z4 z)
{
  extern __shared__ char smem[];
  const int bz=blockIdx.z;
  const __nv_bfloat16* Ah=z.Ah[bz]; const __nv_bfloat16* Al=z.Al[bz];
  const __nv_bfloat16* Bh=z.Bh[bz]; const __nv_bfloat16* Bl=z.Bl[bz];
  __nv_bfloat16* Ch=z.Ch[bz]; __nv_bfloat16* Cl=z.Cl[bz];
  const int tid=threadIdx.x, lane=tid&31, warp=tid>>5, wm=warp&3, wn=warp>>2;
  const int bm=blockIdx.y*128, bn=blockIdx.x*128;
  uint32_t sb=s2u(smem);

  float c[2][8][4];
#pragma unroll
  for(int i=0;i<2;i++)
#pragma unroll
    for(int j=0;j<8;j++){c[i][j][0]=0;c[i][j][1]=0;c[i][j][2]=0;c[i][j][3]=0;}

  const __nv_bfloat16* aptr[4]; uint32_t soA[4];
  const __nv_bfloat16* bptr[4]; uint32_t soB[4];
#pragma unroll
  for(int j=0;j<4;j++){
    int idx=tid+j*256, mm=idx>>9, id2=idx&511, r=id2>>2, c16=id2&3;
    aptr[j]=(mm?Al:Ah)+(size_t)(bm+r)*1024+c16*8;
    soA[j]=mm*8192+toff(r,c16*16);
    bptr[j]=(mm?Bl:Bh)+(size_t)(bn+r)*1024+c16*8;
    soB[j]=16384+mm*8192+toff(r,c16*16);
  }
#pragma unroll
  for(int j=0;j<4;j++){
    *(uint4*)(smem+soA[j])=*(const uint4*)(aptr[j]);
    *(uint4*)(smem+soB[j])=*(const uint4*)(bptr[j]);
  }
  __syncthreads();

  for(int kc=0;kc<32;kc++){
    int cur=kc&1;
    uint4 ua[4],ub[4];
    if(kc<31){
      int k0=(kc+1)<<5;
#pragma unroll
      for(int j=0;j<4;j++){
        ua[j]=*(const uint4*)(aptr[j]+k0);
        ub[j]=*(const uint4*)(bptr[j]+k0);
      }
    }
    compute_chunk(sb+cur*32768,c,wm,wn,lane);
    if(kc<31){
      char* nb=smem+(cur^1)*32768;
#pragma unroll
      for(int j=0;j<4;j++){
        *(uint4*)(nb+soA[j])=ua[j];
        *(uint4*)(nb+soB[j])=ub[j];
      }
    }
    __syncthreads();
  }

#pragma unroll
  for(int mt=0;mt<2;mt++){
#pragma unroll
    for(int half=0;half<2;half++){
      int gm=bm+wm*32+mt*16+(lane>>2)+half*8;
      size_t rowoff=(size_t)gm*1024+bn+wn*64+(lane&3)*2;
#pragma unroll
      for(int f=0;f<8;f++){
        float v0=c[mt][f][half*2], v1=c[mt][f][half*2+1];
        __nv_bfloat16 h0,l0,h1,l1; sp(v0,h0,l0); sp(v1,h1,l1);
        *(uint32_t*)(Ch+rowoff+f*8)=pk(h0,h1);
        *(uint32_t*)(Cl+rowoff+f*8)=pk(l0,l1);
      }
    }
  }
}

// ---------- gate GEMM with fused epilogues ----------
struct G8P{ const __nv_bfloat16* h[8]; const __nv_bfloat16* l[8]; };
__global__ void __launch_bounds__(256,1) gate_mma(
    int Ktot,int NC,int mode,
    const __nv_bfloat16* Wh,const __nv_bfloat16* Wl,
    G8P g,const float* bias,
    float* Hf,float* U,
    __nv_bfloat16* RHh,__nv_bfloat16* RHl,
    __nv_bfloat16* Hh,__nv_bfloat16* Hl,
    float* Z)
{
  extern __shared__ char smem[];
  const int tid=threadIdx.x, lane=tid&31, warp=tid>>5, wm=warp&3, wn=warp>>2;
  const int bn=blockIdx.x*128, b=blockIdx.y;
  uint32_t sb=s2u(smem);

  float c[2][8][4];
#pragma unroll
  for(int i=0;i<2;i++)
#pragma unroll
    for(int j=0;j<8;j++){c[i][j][0]=0;c[i][j][1]=0;c[i][j][2]=0;c[i][j][3]=0;}

  const __nv_bfloat16* wptr[4]; uint32_t soW[4];
#pragma unroll
  for(int j=0;j<4;j++){
    int idx=tid+j*256, mm=idx>>9, id2=idx&511, r=id2>>2, c16=id2&3;
    wptr[j]=(mm?Wl:Wh)+(size_t)r*Ktot+c16*8;
    soW[j]=mm*8192+toff(r,c16*16);
  }
  {
    const __nv_bfloat16* srch=g.h[0]+(size_t)b*65536;
    const __nv_bfloat16* srcl=g.l[0]+(size_t)b*65536;
#pragma unroll
    for(int j=0;j<4;j++)
      *(uint4*)(smem+soW[j])=*(const uint4*)(wptr[j]);
#pragma unroll
    for(int j=0;j<4;j++){
      int idx=tid+j*256, kk=idx>>5, v4=idx&31;
      uint2 vh=*(const uint2*)(srch+(size_t)kk*1024+bn+v4*4);
      uint2 vl=*(const uint2*)(srcl+(size_t)kk*1024+bn+v4*4);
      int r0=v4*4;
      *(uint16_t*)(smem+16384+toff(r0  ,kk*2))=(uint16_t)(vh.x);
      *(uint16_t*)(smem+16384+toff(r0+1,kk*2))=(uint16_t)(vh.x>>16);
      *(uint16_t*)(smem+16384+toff(r0+2,kk*2))=(uint16_t)(vh.y);
      *(uint16_t*)(smem+16384+toff(r0+3,kk*2))=(uint16_t)(vh.y>>16);
      *(uint16_t*)(smem+24576+toff(r0  ,kk*2))=(uint16_t)(vl.x);
      *(uint16_t*)(smem+24576+toff(r0+1,kk*2))=(uint16_t)(vl.x>>16);
      *(uint16_t*)(smem+24576+toff(r0+2,kk*2))=(uint16_t)(vl.y);
      *(uint16_t*)(smem+24576+toff(r0+3,kk*2))=(uint16_t)(vl.y>>16);
    }
  }
  __syncthreads();

  for(int kc=0;kc<NC;kc++){
    int cur=kc&1;
    uint4 uw[4]; uint2 vh[4],vl[4];
    if(kc+1<NC){
      int kn=kc+1, k0=kn<<5;
      const __nv_bfloat16* srch=g.h[kn>>1]+(size_t)(kn&1)*32768+(size_t)b*65536;
      const __nv_bfloat16* srcl=g.l[kn>>1]+(size_t)(kn&1)*32768+(size_t)b*65536;
#pragma unroll
      for(int j=0;j<4;j++) uw[j]=*(const uint4*)(wptr[j]+k0);
#pragma unroll
      for(int j=0;j<4;j++){
        int idx=tid+j*256, kk=idx>>5, v4=idx&31;
        vh[j]=*(const uint2*)(srch+(size_t)kk*1024+bn+v4*4);
        vl[j]=*(const uint2*)(srcl+(size_t)kk*1024+bn+v4*4);
      }
    }
    compute_chunk(sb+cur*32768,c,wm,wn,lane);
    if(kc+1<NC){
      char* nb=smem+(cur^1)*32768;
#pragma unroll
      for(int j=0;j<4;j++)
        *(uint4*)(nb+soW[j])=uw[j];
#pragma unroll
      for(int j=0;j<4;j++){
        int idx=tid+j*256, kk=idx>>5, v4=idx&31;
        int r0=v4*4;
        *(uint16_t*)(nb+16384+toff(r0  ,kk*2))=(uint16_t)(vh[j].x);
        *(uint16_t*)(nb+16384+toff(r0+1,kk*2))=(uint16_t)(vh[j].x>>16);
        *(uint16_t*)(nb+16384+toff(r0+2,kk*2))=(uint16_t)(vh[j].y);
        *(uint16_t*)(nb+16384+toff(r0+3,kk*2))=(uint16_t)(vh[j].y>>16);
        *(uint16_t*)(nb+24576+toff(r0  ,kk*2))=(uint16_t)(vl[j].x);
        *(uint16_t*)(nb+24576+toff(r0+1,kk*2))=(uint16_t)(vl[j].x>>16);
        *(uint16_t*)(nb+24576+toff(r0+2,kk*2))=(uint16_t)(vl[j].y);
        *(uint16_t*)(nb+24576+toff(r0+3,kk*2))=(uint16_t)(vl[j].y>>16);
      }
    }
    __syncthreads();
  }

#pragma unroll
  for(int mt=0;mt<2;mt++){
#pragma unroll
    for(int half=0;half<2;half++){
      int m=wm*32+mt*16+(lane>>2)+half*8;
      int col=bn+wn*64+(lane&3)*2;
      if(mode==0){
        float bv=bias[m];
        if(m<64){
          size_t ro=(size_t)(b*64+m)*1024+col;
#pragma unroll
          for(int f=0;f<8;f++){
            float2 hv=*(const float2*)(Hf+ro+f*8);
            float r0=sgm(c[mt][f][half*2]+bv), r1=sgm(c[mt][f][half*2+1]+bv);
            float x0=r0*hv.x, x1=r1*hv.y;
            __nv_bfloat16 h0,l0,h1,l1; sp(x0,h0,l0); sp(x1,h1,l1);
            *(uint32_t*)(RHh+ro+f*8)=pk(h0,h1);
            *(uint32_t*)(RHl+ro+f*8)=pk(l0,l1);
          }
        } else {
          size_t ro=(size_t)(b*64+(m-64))*1024+col;
#pragma unroll
          for(int f=0;f<8;f++){
            float2 v; v.x=sgm(c[mt][f][half*2]+bv); v.y=sgm(c[mt][f][half*2+1]+bv);
            *(float2*)(U+ro+f*8)=v;
          }
        }
      } else if(mode==1){
        if(m<64){
          float bv=bias[m];
          size_t ro=(size_t)(b*64+m)*1024+col;
#pragma unroll
          for(int f=0;f<8;f++){
            float2 uu=*(const float2*)(U+ro+f*8);
            float2 hh=*(const float2*)(Hf+ro+f*8);
            float c0=tanhf(c[mt][f][half*2]+bv), c1=tanhf(c[mt][f][half*2+1]+bv);
            float n0=uu.x*hh.x+(1.f-uu.x)*c0;
            float n1=uu.y*hh.y+(1.f-uu.y)*c1;
            float2 v; v.x=n0; v.y=n1;
            *(float2*)(Hf+ro+f*8)=v;
            __nv_bfloat16 h0,l0,h1,l1; sp(n0,h0,l0); sp(n1,h1,l1);
            *(uint32_t*)(Hh+ro+f*8)=pk(h0,h1);
            *(uint32_t*)(Hl+ro+f*8)=pk(l0,l1);
          }
        }
      } else {
        if(m<64){
          float bv=bias[m];
          size_t ro=(size_t)(b*64+m)*1024+col;
#pragma unroll
          for(int f=0;f<8;f++){
            float2 v; v.x=c[mt][f][half*2]+bv; v.y=c[mt][f][half*2+1]+bv;
            *(float2*)(Z+ro+f*8)=v;
          }
        }
      }
    }
  }
}

// ---------- small kernels ----------
__global__ void k_normprep(const float* adj,float* rs,float* cs){
  int i=blockIdx.x,t=threadIdx.x; float r=0,c=0;
  for(int j=t;j<1024;j+=256){r+=adj[(size_t)i*1024+j];c+=adj[(size_t)j*1024+i];}
  __shared__ float sr[256],sc[256]; sr[t]=r;sc[t]=c;__syncthreads();
  for(int s=128;s>0;s>>=1){if(t<s){sr[t]+=sr[t+s];sc[t]+=sc[t+s];}__syncthreads();}
  if(t==0){rs[i]=sr[0];cs[i]=sc[0];}
}
__global__ void k_norm_cvt(const float* adj,const float* rs,const float* cs,
    __nv_bfloat16* AFh,__nv_bfloat16* AFl,__nv_bfloat16* ABh,__nv_bfloat16* ABl,
    __nv_bfloat16* AFth,__nv_bfloat16* AFtl,__nv_bfloat16* ABth,__nv_bfloat16* ABtl){
  size_t i=(size_t)blockIdx.x*256+threadIdx.x;
  int w=(int)(i>>10),v=(int)(i&1023);
  size_t ti=(size_t)v*1024+w;
  __nv_bfloat16 h,l;
  sp(adj[i]/rs[w],h,l); AFh[i]=h; AFl[i]=l; AFth[ti]=h; AFtl[ti]=l;
  sp(adj[ti]/cs[w],h,l); ABh[i]=h; ABl[i]=l; ABth[ti]=h; ABtl[ti]=l;
}
__global__ void k_cvt(const float* s,__nv_bfloat16* h,__nv_bfloat16* l,int n){
  int i=blockIdx.x*256+threadIdx.x;
  if(i<n){__nv_bfloat16 hh,ll;sp(s[i],hh,ll);h[i]=hh;l[i]=ll;}
}
__global__ void k_embT(const float* emb,float* et){
  int i=blockIdx.x*256+threadIdx.x;
  et[i]=emb[(size_t)(i&1023)*64+(i>>10)];
}
__global__ void k_encoder(const float* x,const float* We,const float* be,
                          const float* embT,__nv_bfloat16* XEh,__nv_bfloat16* XEl){
  int t=blockIdx.z,b=blockIdx.y,v0=blockIdx.x*32;
  __shared__ float xv[32][8];
  int tid=threadIdx.y*32+threadIdx.x;
  xv[tid>>3][tid&7]=x[(((size_t)b*12+t)*1024+v0)*8+tid];
  __syncthreads();
  int tx=threadIdx.x;
  for(int hh=0;hh<8;hh++){
    int h=threadIdx.y*8+hh;
    float s=be[h]+embT[(size_t)h*1024+v0+tx];
#pragma unroll
    for(int f=0;f<8;f++) s+=xv[tx][f]*We[f*64+h];
    __nv_bfloat16 bh,bl; sp(s,bh,bl);
    size_t o=(size_t)t*M1+(size_t)(b*64+h)*1024+v0+tx;
    XEh[o]=bh; XEl[o]=bl;
  }
}
__global__ void k_packRUT(const float* Wr,const float* Wu,const float* br,const float* bu,
    __nv_bfloat16* Wh,__nv_bfloat16* Wl,float* bru){
  int i=blockIdx.x*256+threadIdx.x;
  if(i<65536){int j=i>>9,k=i&511;
    float w=(j<64)?Wr[k*64+j]:Wu[k*64+j-64];
    __nv_bfloat16 h,l;sp(w,h,l);Wh[i]=h;Wl[i]=l;}
  if(i<128) bru[i]=(i<64)?br[i]:bu[i-64];
}
__global__ void k_packT(const float* W,__nv_bfloat16* Wh,__nv_bfloat16* Wl,int Kd){
  int i=blockIdx.x*256+threadIdx.x;
  if(i<128*Kd){int j=i/Kd,k=i-j*Kd;
    float w=(j<64)?W[k*64+j]:0.f;
    __nv_bfloat16 h,l;sp(w,h,l);Wh[i]=h;Wl[i]=l;}
}
__global__ void k_deg(const int* src,const int* dst,const float* w,
                      float* dd,float* ds,int E){
  int e=blockIdx.x*256+threadIdx.x;
  if(e<E){atomicAdd(&dd[dst[e]],w[e]);atomicAdd(&ds[src[e]],w[e]);}
}
__global__ void k_buildW(const int* src,const int* dst,const float* w,
    const float* dd,const float* ds,float* Wf,float* Wb,int E){
  int e=blockIdx.x*256+threadIdx.x;
  if(e<E){int s=src[e],d=dst[e];float we=w[e];
    float a=dd[d],b2=ds[s];
    atomicAdd(&Wf[(size_t)d*1024+s],(a>0.f)?we/a:0.f);
    atomicAdd(&Wb[(size_t)s*1024+d],(b2>0.f)?we/b2:0.f);}
}
__global__ void k_decoder(const float* Z,const float* Wd,const float* bd,float* out){
  int bn=blockIdx.x*128,b=blockIdx.y,tx=threadIdx.x;
  __shared__ float Ws[64*96],bs[96];
  for(int i=tx;i<6144;i+=128) Ws[i]=Wd[i];
  if(tx<96) bs[tx]=bd[tx];
  __syncthreads();
  int v=bn+tx;
  float z[64];
#pragma unroll
  for(int h=0;h<64;h++) z[h]=Z[(size_t)(b*64+h)*1024+v];
  for(int j=0;j<96;j++){
    float s=bs[j];
#pragma unroll
    for(int h=0;h<64;h++) s+=z[h]*Ws[h*96+j];
    out[(((size_t)b*12+(j>>3))*1024+v)*8+(j&7)]=s;
  }
}

// ---------- driver ----------
extern "C" void kernel_launch(void* const* d_in,const int* in_sizes,int n_in,
                              void* d_out,int out_size){
  const float* x=(const float*)d_in[0];
  const int* ei=(const int*)d_in[1];
  const float* ew=(const float*)d_in[2];
  const float* adj=(const float*)d_in[3];
  const float* Wenc=(const float*)d_in[4];
  const float* benc=(const float*)d_in[5];
  const float* nemb=(const float*)d_in[6];
  const float* Wr=(const float*)d_in[7];  const float* br=(const float*)d_in[8];
  const float* Wu=(const float*)d_in[9];  const float* bu=(const float*)d_in[10];
  const float* Wc=(const float*)d_in[11]; const float* bc=(const float*)d_in[12];
  const float* Wdiff=(const float*)d_in[13]; const float* bdiff=(const float*)d_in[14];
  const float* Wdec=(const float*)d_in[15];  const float* bdec=(const float*)d_in[16];
  float* out=(float*)d_out;
  const int E=in_sizes[2];
  const int* src=ei; const int* dst=ei+E;

  float* B=nullptr; cudaGetSymbolAddress((void**)&B,g_buf);
#define BP(o) ((__nv_bfloat16*)(B+(o)))
  float *Hf=B+O_Hf,*U=B+O_U,*Z=B+O_Z,*WFf=B+O_WFf,*EMBT=B+O_EMBT,
        *BRU=B+O_BRU,*RS=B+O_RS,*CS=B+O_CS,*DGD=B+O_DGD;
  __nv_bfloat16 *XEh=BP(O_XEh),*XEl=BP(O_XEl),
   *Hh=BP(O_Hh),*Hl=BP(O_Hl),*RHh=BP(O_RHh),*RHl=BP(O_RHl),
   *AFh=BP(O_AFh),*AFl=BP(O_AFl),*A2Fh=BP(O_A2Fh),*A2Fl=BP(O_A2Fl),
   *ABh=BP(O_ABh),*ABl=BP(O_ABl),*A2Bh=BP(O_A2Bh),*A2Bl=BP(O_A2Bl),
   *AFth=BP(O_AFth),*AFtl=BP(O_AFtl),*ABth=BP(O_ABth),*ABtl=BP(O_ABtl),
   *WFh=BP(O_WFh),*WFl=BP(O_WFl),*WBh=BP(O_WBh),*WBl=BP(O_WBl),
   *RUh=BP(O_RUh),*RUl=BP(O_RUl),*WCh=BP(O_WCh),*WCl=BP(O_WCl),
   *WDh=BP(O_WDh),*WDl=BP(O_WDl);
  const __nv_bfloat16* Sh[4]={AFh,A2Fh,ABh,A2Bh};
  const __nv_bfloat16* Sl[4]={AFl,A2Fl,ABl,A2Bl};

  cudaFuncSetAttribute(hop_mma,cudaFuncAttributeMaxDynamicSharedMemorySize,SMEMB);
  cudaFuncSetAttribute(gate_mma,cudaFuncAttributeMaxDynamicSharedMemorySize,SMEMB);

  k_normprep<<<1024,256>>>(adj,RS,CS);
  k_norm_cvt<<<4096,256>>>(adj,RS,CS,AFh,AFl,ABh,ABl,AFth,AFtl,ABth,ABtl);
  k_embT<<<256,256>>>(nemb,EMBT);
  k_encoder<<<dim3(32,16,12),dim3(32,8)>>>(x,Wenc,benc,EMBT,XEh,XEl);
  k_packRUT<<<256,256>>>(Wr,Wu,br,bu,RUh,RUl,BRU);
  k_packT<<<256,256>>>(Wc,WCh,WCl,512);
  k_packT<<<160,256>>>(Wdiff,WDh,WDl,320);
  cudaMemsetAsync(Hf,0,(size_t)2*M1*4);   // Hf + H pairs

  // A^2 for both supports
  {
    Z4 z;
    z.Ah[0]=AFh; z.Al[0]=AFl; z.Bh[0]=AFth; z.Bl[0]=AFtl; z.Ch[0]=A2Fh; z.Cl[0]=A2Fl;
    z.Ah[1]=ABh; z.Al[1]=ABl; z.Bh[1]=ABth; z.Bl[1]=ABtl; z.Ch[1]=A2Bh; z.Cl[1]=A2Bl;
    z.Ah[2]=AFh; z.Al[2]=AFl; z.Bh[2]=AFth; z.Bl[2]=AFtl; z.Ch[2]=A2Fh; z.Cl[2]=A2Fl;
    z.Ah[3]=AFh; z.Al[3]=AFl; z.Bh[3]=AFth; z.Bl[3]=AFtl; z.Ch[3]=A2Fh; z.Cl[3]=A2Fl;
    hop_mma<<<dim3(8,8,2),256,SMEMB>>>(z);
  }
  // all x-hops for all t, all 4 supports, one launch
  {
    Z4 z;
    for(int s=0;s<4;s++){
      z.Ah[s]=XEh; z.Al[s]=XEl;
      z.Bh[s]=Sh[s]; z.Bl[s]=Sl[s];
      z.Ch[s]=BP(O_XHh+(size_t)s*6*M1);
      z.Cl[s]=BP(O_XHl+(size_t)s*6*M1);
    }
    hop_mma<<<dim3(8,96,4),256,SMEMB>>>(z);
  }

  Z4 zh, zt;
  for(int s=0;s<4;s++){
    zh.Ah[s]=Hh; zh.Al[s]=Hl; zh.Bh[s]=Sh[s]; zh.Bl[s]=Sl[s];
    zh.Ch[s]=BP(O_HHh+(size_t)s*HK); zh.Cl[s]=BP(O_HHl+(size_t)s*HK);
    zt.Ah[s]=RHh; zt.Al[s]=RHl; zt.Bh[s]=Sh[s]; zt.Bl[s]=Sl[s];
    zt.Ch[s]=BP(O_THh+(size_t)s*HK); zt.Cl[s]=BP(O_THl+(size_t)s*HK);
  }

  dim3 gHop(8,8,4), gGate(8,16);
  for(int t=0;t<12;t++){
    G8P gru,gcc;
    for(int s=0;s<4;s++){
      gru.h[2*s]=BP(O_XHh+(size_t)s*6*M1+(size_t)t*HK);
      gru.l[2*s]=BP(O_XHl+(size_t)s*6*M1+(size_t)t*HK);
      gru.h[2*s+1]=BP(O_HHh+(size_t)s*HK);
      gru.l[2*s+1]=BP(O_HHl+(size_t)s*HK);
      gcc.h[2*s]=gru.h[2*s]; gcc.l[2*s]=gru.l[2*s];
      gcc.h[2*s+1]=BP(O_THh+(size_t)s*HK);
      gcc.l[2*s+1]=BP(O_THl+(size_t)s*HK);
    }
    hop_mma<<<gHop,256,SMEMB>>>(zh);
    gate_mma<<<gGate,256,SMEMB>>>(512,16,0,RUh,RUl,gru,BRU,Hf,U,RHh,RHl,Hh,Hl,Z);
    hop_mma<<<gHop,256,SMEMB>>>(zt);
    gate_mma<<<gGate,256,SMEMB>>>(512,16,1,WCh,WCl,gcc,bc,Hf,U,RHh,RHl,Hh,Hl,Z);
  }

  // ---- DiffConv readout ----
  cudaMemsetAsync(WFf,0,(size_t)2*M1*4);
  cudaMemsetAsync(DGD,0,2048*4);
  k_deg<<<(E+255)/256,256>>>(src,dst,ew,DGD,DGD+1024,E);
  k_buildW<<<(E+255)/256,256>>>(src,dst,ew,DGD,DGD+1024,WFf,WFf+M1,E);
  k_cvt<<<4096,256>>>(WFf,WFh,WFl,(int)M1);
  k_cvt<<<4096,256>>>(WFf+M1,WBh,WBl,(int)M1);

  {
    Z4 z;
    z.Ah[0]=Hh; z.Al[0]=Hl; z.Bh[0]=WFh; z.Bl[0]=WFl; z.Ch[0]=BP(O_D1Fh); z.Cl[0]=BP(O_D1Fl);
    z.Ah[1]=Hh; z.Al[1]=Hl; z.Bh[1]=WBh; z.Bl[1]=WBl; z.Ch[1]=BP(O_D1Bh); z.Cl[1]=BP(O_D1Bl);
    z.Ah[2]=Hh; z.Al[2]=Hl; z.Bh[2]=WFh; z.Bl[2]=WFl; z.Ch[2]=BP(O_D1Fh); z.Cl[2]=BP(O_D1Fl);
    z.Ah[3]=Hh; z.Al[3]=Hl; z.Bh[3]=WFh; z.Bl[3]=WFl; z.Ch[3]=BP(O_D1Fh); z.Cl[3]=BP(O_D1Fl);
    hop_mma<<<dim3(8,8,2),256,SMEMB>>>(z);
    Z4 z2;
    z2.Ah[0]=BP(O_D1Fh); z2.Al[0]=BP(O_D1Fl); z2.Bh[0]=WFh; z2.Bl[0]=WFl;
    z2.Ch[0]=BP(O_D2Fh); z2.Cl[0]=BP(O_D2Fl);
    z2.Ah[1]=BP(O_D1Bh); z2.Al[1]=BP(O_D1Bl); z2.Bh[1]=WBh; z2.Bl[1]=WBl;
    z2.Ch[1]=BP(O_D2Bh); z2.Cl[1]=BP(O_D2Bl);
    z2.Ah[2]=z2.Ah[0]; z2.Al[2]=z2.Al[0]; z2.Bh[2]=WFh; z2.Bl[2]=WFl;
    z2.Ch[2]=z2.Ch[0]; z2.Cl[2]=z2.Cl[0];
    z2.Ah[3]=z2.Ah[0]; z2.Al[3]=z2.Al[0]; z2.Bh[3]=WFh; z2.Bl[3]=WFl;
    z2.Ch[3]=z2.Ch[0]; z2.Cl[3]=z2.Cl[0];
    hop_mma<<<dim3(8,8,2),256,SMEMB>>>(z2);
  }
  {
    G8P gd;
    gd.h[0]=Hh;        gd.l[0]=Hl;
    gd.h[1]=BP(O_D1Fh);gd.l[1]=BP(O_D1Fl);
    gd.h[2]=BP(O_D2Fh);gd.l[2]=BP(O_D2Fl);
    gd.h[3]=BP(O_D1Bh);gd.l[3]=BP(O_D1Bl);
    gd.h[4]=BP(O_D2Bh);gd.l[4]=BP(O_D2Bl);
    gd.h[5]=Hh; gd.l[5]=Hl; gd.h[6]=Hh; gd.l[6]=Hl; gd.h[7]=Hh; gd.l[7]=Hl;
    gate_mma<<<gGate,256,SMEMB>>>(320,10,2,WDh,WDl,gd,bdiff,Hf,U,RHh,RHl,Hh,Hl,Z);
  }
  k_decoder<<<dim3(8,16),128>>>(Z,Wdec,bdec,out);
}

// round 13
// speedup vs baseline: 3.5974x; 1.4827x over previous
#include <cuda_runtime.h>
#include <cuda_fp16.h>
#include <math.h>
#include <stdint.h>

#define M1 ((size_t)1<<20)
#define HK ((size_t)1<<19)
// float-unit offsets (fp16 planes are same byte size as before)
constexpr size_t O_XEh=0, O_XEl=6*M1,
 O_XHh=12*M1, O_XHl=36*M1,            // per support s: +s*6*M1, per t: +t*HK
 O_HHh=60*M1, O_HHl=62*M1,            // per s: +s*HK
 O_THh=64*M1, O_THl=66*M1,
 O_Hf=68*M1, O_Hh=69*M1, O_Hl=69*M1+HK,
 O_RHh=70*M1, O_RHl=70*M1+HK,
 O_U=71*M1, O_Z=72*M1,
 O_D1Fh=73*M1, O_D1Fl=73*M1+HK, O_D1Bh=74*M1, O_D1Bl=74*M1+HK,
 O_D2Fh=75*M1, O_D2Fl=75*M1+HK, O_D2Bh=76*M1, O_D2Bl=76*M1+HK,
 O_WFf=77*M1,
 O_AFh=79*M1, O_AFl=79*M1+HK, O_A2Fh=80*M1, O_A2Fl=80*M1+HK,
 O_ABh=81*M1, O_ABl=81*M1+HK, O_A2Bh=82*M1, O_A2Bl=82*M1+HK,
 O_AFth=83*M1, O_AFtl=83*M1+HK, O_ABth=84*M1, O_ABtl=84*M1+HK,
 O_WFh=85*M1, O_WFl=85*M1+HK, O_WBh=86*M1, O_WBl=86*M1+HK,
 O_EMBT=87*M1,
 O_RUh=O_EMBT+65536, O_RUl=O_RUh+32768,
 O_WCh=O_RUl+32768, O_WCl=O_WCh+32768,
 O_WDh=O_WCl+32768, O_WDl=O_WDh+20480,
 O_BRU=O_WDl+20480, O_RS=O_BRU+128, O_CS=O_RS+1024, O_DGD=O_CS+1024,
 O_END=O_DGD+2048;
__device__ float g_buf[O_END];

// ---------- helpers ----------
__device__ __forceinline__ uint32_t s2u(const void*p){uint32_t a;asm("{ .reg .u64 t; cvta.to.shared.u64 t, %1; cvt.u32.u64 %0, t; }":"=r"(a):"l"(p));return a;}
__device__ __forceinline__ void sph(float x,__half&h,__half&l){h=__float2half(x);l=__float2half(x-__half2float(h));}
__device__ __forceinline__ uint32_t pkh(__half a,__half b){__half2 t;t.x=a;t.y=b;return *(uint32_t*)&t;}
__device__ __forceinline__ void ldsm4(uint32_t* r,uint32_t addr){
  asm volatile("ldmatrix.sync.aligned.m8n8.x4.shared.b16 {%0,%1,%2,%3}, [%4];"
   : "=r"(r[0]),"=r"(r[1]),"=r"(r[2]),"=r"(r[3]) : "r"(addr));
}
__device__ __forceinline__ void mmaf(float* c,const uint32_t* a,uint32_t b0,uint32_t b1){
  asm volatile("mma.sync.aligned.m16n8k16.row.col.f32.f16.f16.f32 "
    "{%0,%1,%2,%3}, {%4,%5,%6,%7}, {%8,%9}, {%0,%1,%2,%3};"
    : "+f"(c[0]),"+f"(c[1]),"+f"(c[2]),"+f"(c[3])
    : "r"(a[0]),"r"(a[1]),"r"(a[2]),"r"(a[3]),"r"(b0),"r"(b1));
}
__device__ __forceinline__ uint32_t toff(int r,int kbyte){return r*64 + (kbyte ^ ((r&3)<<4));}
__device__ __forceinline__ float sgm(float x){return 1.f/(1.f+expf(-x));}
// chunk buffer: [Ah 8K][Al 8K][Bh 8K] = 24576; double-buffered
#define CHB 24576
#define SMEMB 49152

// per-warp compute of one K=32 chunk, 2-term: (Ah+Al)*Bh
__device__ __forceinline__ void compute_chunk(uint32_t sbase,float c[2][8][4],
                                              int wm,int wn,int lane){
  const int ar=(lane&15), acs=((lane>>4)<<4);
  const int lr=lane&7, sel=lane>>3;
  const int brb=wn*64+((sel>>1)<<3)+lr, bcs=(sel&1)<<4;
#pragma unroll
  for(int s=0;s<2;s++){
    uint32_t a[2][2][4], b[4][4];
#pragma unroll
    for(int mt=0;mt<2;mt++){
      int r=wm*32+mt*16+ar;
      uint32_t off=toff(r,s*32+acs);
      ldsm4(a[mt][0],sbase+off);
      ldsm4(a[mt][1],sbase+8192+off);
    }
#pragma unroll
    for(int g=0;g<4;g++){
      int r=brb+g*16;
      ldsm4(b[g],sbase+16384+toff(r,s*32+bcs));
    }
#pragma unroll
    for(int mt=0;mt<2;mt++)
#pragma unroll
      for(int g=0;g<4;g++){
        mmaf(c[mt][2*g],  a[mt][0],b[g][0],b[g][1]);
        mmaf(c[mt][2*g],  a[mt][1],b[g][0],b[g][1]);
        mmaf(c[mt][2*g+1],a[mt][0],b[g][2],b[g][3]);
        mmaf(c[mt][2*g+1],a[mt][1],b[g][2],b[g][3]);
      }
  }
}

// ---------- hop GEMM: C[m][n] = sum_v A[m][v]*B[n][v] ----------
struct Z4 {
  const __half *Ah[4],*Al[4],*Bh[4];
  __half *Ch[4],*Cl[4];
};
__global__ void __launch_bounds__(256,1) hop_mma(Z4 z)
{
  extern __shared__ char smem[];
  const int bz=blockIdx.z;
  const __half* Ah=z.Ah[bz]; const __half* Al=z.Al[bz];
  const __half* Bh=z.Bh[bz];
  __half* Ch=z.Ch[bz]; __half* Cl=z.Cl[bz];
  const int tid=threadIdx.x, lane=tid&31, warp=tid>>5, wm=warp&3, wn=warp>>2;
  const int bm=blockIdx.y*128, bn=blockIdx.x*128;
  uint32_t sb=s2u(smem);

  float c[2][8][4];
#pragma unroll
  for(int i=0;i<2;i++)
#pragma unroll
    for(int j=0;j<8;j++){c[i][j][0]=0;c[i][j][1]=0;c[i][j][2]=0;c[i][j][3]=0;}

  const __half* aptr[4]; uint32_t soA[4];
  const __half* bptr[2]; uint32_t soB[2];
#pragma unroll
  for(int j=0;j<4;j++){
    int idx=tid+j*256, mm=idx>>9, id2=idx&511, r=id2>>2, c16=id2&3;
    aptr[j]=(mm?Al:Ah)+(size_t)(bm+r)*1024+c16*8;
    soA[j]=mm*8192+toff(r,c16*16);
  }
#pragma unroll
  for(int j=0;j<2;j++){
    int idx=tid+j*256, r=idx>>2, c16=idx&3;
    bptr[j]=Bh+(size_t)(bn+r)*1024+c16*8;
    soB[j]=16384+toff(r,c16*16);
  }
#pragma unroll
  for(int j=0;j<4;j++) *(uint4*)(smem+soA[j])=*(const uint4*)(aptr[j]);
#pragma unroll
  for(int j=0;j<2;j++) *(uint4*)(smem+soB[j])=*(const uint4*)(bptr[j]);
  __syncthreads();

  for(int kc=0;kc<32;kc++){
    int cur=kc&1;
    uint4 ua[4],ub[2];
    if(kc<31){
      int k0=(kc+1)<<5;
#pragma unroll
      for(int j=0;j<4;j++) ua[j]=*(const uint4*)(aptr[j]+k0);
#pragma unroll
      for(int j=0;j<2;j++) ub[j]=*(const uint4*)(bptr[j]+k0);
    }
    compute_chunk(sb+cur*CHB,c,wm,wn,lane);
    if(kc<31){
      char* nb=smem+(cur^1)*CHB;
#pragma unroll
      for(int j=0;j<4;j++) *(uint4*)(nb+soA[j])=ua[j];
#pragma unroll
      for(int j=0;j<2;j++) *(uint4*)(nb+soB[j])=ub[j];
    }
    __syncthreads();
  }

#pragma unroll
  for(int mt=0;mt<2;mt++){
#pragma unroll
    for(int half=0;half<2;half++){
      int gm=bm+wm*32+mt*16+(lane>>2)+half*8;
      size_t rowoff=(size_t)gm*1024+bn+wn*64+(lane&3)*2;
#pragma unroll
      for(int f=0;f<8;f++){
        float v0=c[mt][f][half*2], v1=c[mt][f][half*2+1];
        __half h0,l0,h1,l1; sph(v0,h0,l0); sph(v1,h1,l1);
        *(uint32_t*)(Ch+rowoff+f*8)=pkh(h0,h1);
        *(uint32_t*)(Cl+rowoff+f*8)=pkh(l0,l1);
      }
    }
  }
}

// ---------- gate GEMM with fused epilogues ----------
// A = W pair (hi/lo), B = activations hi-plane only (transposed in-loader)
struct G8P{ const __half* h[8]; };
__global__ void __launch_bounds__(256,1) gate_mma(
    int Ktot,int NC,int mode,
    const __half* Wh,const __half* Wl,
    G8P g,const float* bias,
    float* Hf,float* U,
    __half* RHh,__half* RHl,
    __half* Hh,__half* Hl,
    float* Z)
{
  extern __shared__ char smem[];
  const int tid=threadIdx.x, lane=tid&31, warp=tid>>5, wm=warp&3, wn=warp>>2;
  const int bn=blockIdx.x*128, b=blockIdx.y;
  uint32_t sb=s2u(smem);

  float c[2][8][4];
#pragma unroll
  for(int i=0;i<2;i++)
#pragma unroll
    for(int j=0;j<8;j++){c[i][j][0]=0;c[i][j][1]=0;c[i][j][2]=0;c[i][j][3]=0;}

  const __half* wptr[4]; uint32_t soW[4];
#pragma unroll
  for(int j=0;j<4;j++){
    int idx=tid+j*256, mm=idx>>9, id2=idx&511, r=id2>>2, c16=id2&3;
    wptr[j]=(mm?Wl:Wh)+(size_t)r*Ktot+c16*8;
    soW[j]=mm*8192+toff(r,c16*16);
  }
  {
    const __half* srch=g.h[0]+(size_t)b*65536;
#pragma unroll
    for(int j=0;j<4;j++)
      *(uint4*)(smem+soW[j])=*(const uint4*)(wptr[j]);
#pragma unroll
    for(int j=0;j<4;j++){
      int idx=tid+j*256, kk=idx>>5, v4=idx&31;
      uint2 vh=*(const uint2*)(srch+(size_t)kk*1024+bn+v4*4);
      int r0=v4*4;
      *(uint16_t*)(smem+16384+toff(r0  ,kk*2))=(uint16_t)(vh.x);
      *(uint16_t*)(smem+16384+toff(r0+1,kk*2))=(uint16_t)(vh.x>>16);
      *(uint16_t*)(smem+16384+toff(r0+2,kk*2))=(uint16_t)(vh.y);
      *(uint16_t*)(smem+16384+toff(r0+3,kk*2))=(uint16_t)(vh.y>>16);
    }
  }
  __syncthreads();

  for(int kc=0;kc<NC;kc++){
    int cur=kc&1;
    uint4 uw[4]; uint2 vh[4];
    if(kc+1<NC){
      int kn=kc+1, k0=kn<<5;
      const __half* srch=g.h[kn>>1]+(size_t)(kn&1)*32768+(size_t)b*65536;
#pragma unroll
      for(int j=0;j<4;j++) uw[j]=*(const uint4*)(wptr[j]+k0);
#pragma unroll
      for(int j=0;j<4;j++){
        int idx=tid+j*256, kk=idx>>5, v4=idx&31;
        vh[j]=*(const uint2*)(srch+(size_t)kk*1024+bn+v4*4);
      }
    }
    compute_chunk(sb+cur*CHB,c,wm,wn,lane);
    if(kc+1<NC){
      char* nb=smem+(cur^1)*CHB;
#pragma unroll
      for(int j=0;j<4;j++)
        *(uint4*)(nb+soW[j])=uw[j];
#pragma unroll
      for(int j=0;j<4;j++){
        int idx=tid+j*256, kk=idx>>5, v4=idx&31;
        int r0=v4*4;
        *(uint16_t*)(nb+16384+toff(r0  ,kk*2))=(uint16_t)(vh[j].x);
        *(uint16_t*)(nb+16384+toff(r0+1,kk*2))=(uint16_t)(vh[j].x>>16);
        *(uint16_t*)(nb+16384+toff(r0+2,kk*2))=(uint16_t)(vh[j].y);
        *(uint16_t*)(nb+16384+toff(r0+3,kk*2))=(uint16_t)(vh[j].y>>16);
      }
    }
    __syncthreads();
  }

#pragma unroll
  for(int mt=0;mt<2;mt++){
#pragma unroll
    for(int half=0;half<2;half++){
      int m=wm*32+mt*16+(lane>>2)+half*8;
      int col=bn+wn*64+(lane&3)*2;
      if(mode==0){
        float bv=bias[m];
        if(m<64){
          size_t ro=(size_t)(b*64+m)*1024+col;
#pragma unroll
          for(int f=0;f<8;f++){
            float2 hv=*(const float2*)(Hf+ro+f*8);
            float r0=sgm(c[mt][f][half*2]+bv), r1=sgm(c[mt][f][half*2+1]+bv);
            float x0=r0*hv.x, x1=r1*hv.y;
            __half h0,l0,h1,l1; sph(x0,h0,l0); sph(x1,h1,l1);
            *(uint32_t*)(RHh+ro+f*8)=pkh(h0,h1);
            *(uint32_t*)(RHl+ro+f*8)=pkh(l0,l1);
          }
        } else {
          size_t ro=(size_t)(b*64+(m-64))*1024+col;
#pragma unroll
          for(int f=0;f<8;f++){
            float2 v; v.x=sgm(c[mt][f][half*2]+bv); v.y=sgm(c[mt][f][half*2+1]+bv);
            *(float2*)(U+ro+f*8)=v;
          }
        }
      } else if(mode==1){
        if(m<64){
          float bv=bias[m];
          size_t ro=(size_t)(b*64+m)*1024+col;
#pragma unroll
          for(int f=0;f<8;f++){
            float2 uu=*(const float2*)(U+ro+f*8);
            float2 hh=*(const float2*)(Hf+ro+f*8);
            float c0=tanhf(c[mt][f][half*2]+bv), c1=tanhf(c[mt][f][half*2+1]+bv);
            float n0=uu.x*hh.x+(1.f-uu.x)*c0;
            float n1=uu.y*hh.y+(1.f-uu.y)*c1;
            float2 v; v.x=n0; v.y=n1;
            *(float2*)(Hf+ro+f*8)=v;
            __half h0,l0,h1,l1; sph(n0,h0,l0); sph(n1,h1,l1);
            *(uint32_t*)(Hh+ro+f*8)=pkh(h0,h1);
            *(uint32_t*)(Hl+ro+f*8)=pkh(l0,l1);
          }
        }
      } else {
        if(m<64){
          float bv=bias[m];
          size_t ro=(size_t)(b*64+m)*1024+col;
#pragma unroll
          for(int f=0;f<8;f++){
            float2 v; v.x=c[mt][f][half*2]+bv; v.y=c[mt][f][half*2+1]+bv;
            *(float2*)(Z+ro+f*8)=v;
          }
        }
      }
    }
  }
}

// ---------- small kernels ----------
__global__ void k_normprep(const float* adj,float* rs,float* cs){
  int i=blockIdx.x,t=threadIdx.x; float r=0,c=0;
  for(int j=t;j<1024;j+=256){r+=adj[(size_t)i*1024+j];c+=adj[(size_t)j*1024+i];}
  __shared__ float sr[256],sc[256]; sr[t]=r;sc[t]=c;__syncthreads();
  for(int s=128;s>0;s>>=1){if(t<s){sr[t]+=sr[t+s];sc[t]+=sc[t+s];}__syncthreads();}
  if(t==0){rs[i]=sr[0];cs[i]=cs?sc[0]:sc[0];}
}
__global__ void k_norm_cvt(const float* adj,const float* rs,const float* cs,
    __half* AFh,__half* AFl,__half* ABh,__half* ABl,
    __half* AFth,__half* AFtl,__half* ABth,__half* ABtl){
  size_t i=(size_t)blockIdx.x*256+threadIdx.x;
  int w=(int)(i>>10),v=(int)(i&1023);
  size_t ti=(size_t)v*1024+w;
  __half h,l;
  sph(adj[i]/rs[w],h,l); AFh[i]=h; AFl[i]=l; AFth[ti]=h; AFtl[ti]=l;
  sph(adj[ti]/cs[w],h,l); ABh[i]=h; ABl[i]=l; ABth[ti]=h; ABtl[ti]=l;
}
__global__ void k_cvt(const float* s,__half* h,__half* l,int n){
  int i=blockIdx.x*256+threadIdx.x;
  if(i<n){__half hh,ll;sph(s[i],hh,ll);h[i]=hh;l[i]=ll;}
}
__global__ void k_embT(const float* emb,float* et){
  int i=blockIdx.x*256+threadIdx.x;
  et[i]=emb[(size_t)(i&1023)*64+(i>>10)];
}
__global__ void k_encoder(const float* x,const float* We,const float* be,
                          const float* embT,__half* XEh,__half* XEl){
  int t=blockIdx.z,b=blockIdx.y,v0=blockIdx.x*32;
  __shared__ float xv[32][8];
  int tid=threadIdx.y*32+threadIdx.x;
  xv[tid>>3][tid&7]=x[(((size_t)b*12+t)*1024+v0)*8+tid];
  __syncthreads();
  int tx=threadIdx.x;
  for(int hh=0;hh<8;hh++){
    int h=threadIdx.y*8+hh;
    float s=be[h]+embT[(size_t)h*1024+v0+tx];
#pragma unroll
    for(int f=0;f<8;f++) s+=xv[tx][f]*We[f*64+h];
    __half bh,bl; sph(s,bh,bl);
    size_t o=(size_t)t*M1+(size_t)(b*64+h)*1024+v0+tx;
    XEh[o]=bh; XEl[o]=bl;
  }
}
__global__ void k_packRUT(const float* Wr,const float* Wu,const float* br,const float* bu,
    __half* Wh,__half* Wl,float* bru){
  int i=blockIdx.x*256+threadIdx.x;
  if(i<65536){int j=i>>9,k=i&511;
    float w=(j<64)?Wr[k*64+j]:Wu[k*64+j-64];
    __half h,l;sph(w,h,l);Wh[i]=h;Wl[i]=l;}
  if(i<128) bru[i]=(i<64)?br[i]:bu[i-64];
}
__global__ void k_packT(const float* W,__half* Wh,__half* Wl,int Kd){
  int i=blockIdx.x*256+threadIdx.x;
  if(i<128*Kd){int j=i/Kd,k=i-j*Kd;
    float w=(j<64)?W[k*64+j]:0.f;
    __half h,l;sph(w,h,l);Wh[i]=h;Wl[i]=l;}
}
__global__ void k_deg(const int* src,const int* dst,const float* w,
                      float* dd,float* ds,int E){
  int e=blockIdx.x*256+threadIdx.x;
  if(e<E){atomicAdd(&dd[dst[e]],w[e]);atomicAdd(&ds[src[e]],w[e]);}
}
__global__ void k_buildW(const int* src,const int* dst,const float* w,
    const float* dd,const float* ds,float* Wf,float* Wb,int E){
  int e=blockIdx.x*256+threadIdx.x;
  if(e<E){int s=src[e],d=dst[e];float we=w[e];
    float a=dd[d],b2=ds[s];
    atomicAdd(&Wf[(size_t)d*1024+s],(a>0.f)?we/a:0.f);
    atomicAdd(&Wb[(size_t)s*1024+d],(b2>0.f)?we/b2:0.f);}
}
__global__ void k_decoder(const float* Z,const float* Wd,const float* bd,float* out){
  int bn=blockIdx.x*128,b=blockIdx.y,tx=threadIdx.x;
  __shared__ float Ws[64*96],bs[96];
  for(int i=tx;i<6144;i+=128) Ws[i]=Wd[i];
  if(tx<96) bs[tx]=bd[tx];
  __syncthreads();
  int v=bn+tx;
  float z[64];
#pragma unroll
  for(int h=0;h<64;h++) z[h]=Z[(size_t)(b*64+h)*1024+v];
  for(int j=0;j<96;j++){
    float s=bs[j];
#pragma unroll
    for(int h=0;h<64;h++) s+=z[h]*Ws[h*96+j];
    out[(((size_t)b*12+(j>>3))*1024+v)*8+(j&7)]=s;
  }
}

// ---------- driver ----------
extern "C" void kernel_launch(void* const* d_in,const int* in_sizes,int n_in,
                              void* d_out,int out_size){
  const float* x=(const float*)d_in[0];
  const int* ei=(const int*)d_in[1];
  const float* ew=(const float*)d_in[2];
  const float* adj=(const float*)d_in[3];
  const float* Wenc=(const float*)d_in[4];
  const float* benc=(const float*)d_in[5];
  const float* nemb=(const float*)d_in[6];
  const float* Wr=(const float*)d_in[7];  const float* br=(const float*)d_in[8];
  const float* Wu=(const float*)d_in[9];  const float* bu=(const float*)d_in[10];
  const float* Wc=(const float*)d_in[11]; const float* bc=(const float*)d_in[12];
  const float* Wdiff=(const float*)d_in[13]; const float* bdiff=(const float*)d_in[14];
  const float* Wdec=(const float*)d_in[15];  const float* bdec=(const float*)d_in[16];
  float* out=(float*)d_out;
  const int E=in_sizes[2];
  const int* src=ei; const int* dst=ei+E;

  float* B=nullptr; cudaGetSymbolAddress((void**)&B,g_buf);
#define BP(o) ((__half*)(B+(o)))
  float *Hf=B+O_Hf,*U=B+O_U,*Z=B+O_Z,*WFf=B+O_WFf,*EMBT=B+O_EMBT,
        *BRU=B+O_BRU,*RS=B+O_RS,*CS=B+O_CS,*DGD=B+O_DGD;
  __half *XEh=BP(O_XEh),*XEl=BP(O_XEl),
   *Hh=BP(O_Hh),*Hl=BP(O_Hl),*RHh=BP(O_RHh),*RHl=BP(O_RHl),
   *AFh=BP(O_AFh),*AFl=BP(O_AFl),*A2Fh=BP(O_A2Fh),*A2Fl=BP(O_A2Fl),
   *ABh=BP(O_ABh),*ABl=BP(O_ABl),*A2Bh=BP(O_A2Bh),*A2Bl=BP(O_A2Bl),
   *AFth=BP(O_AFth),*AFtl=BP(O_AFtl),*ABth=BP(O_ABth),*ABtl=BP(O_ABtl),
   *WFh=BP(O_WFh),*WFl=BP(O_WFl),*WBh=BP(O_WBh),*WBl=BP(O_WBl),
   *RUh=BP(O_RUh),*RUl=BP(O_RUl),*WCh=BP(O_WCh),*WCl=BP(O_WCl),
   *WDh=BP(O_WDh),*WDl=BP(O_WDl);
  const __half* Sh[4]={AFh,A2Fh,ABh,A2Bh};

  cudaFuncSetAttribute(hop_mma,cudaFuncAttributeMaxDynamicSharedMemorySize,SMEMB);
  cudaFuncSetAttribute(gate_mma,cudaFuncAttributeMaxDynamicSharedMemorySize,SMEMB);

  k_normprep<<<1024,256>>>(adj,RS,CS);
  k_norm_cvt<<<4096,256>>>(adj,RS,CS,AFh,AFl,ABh,ABl,AFth,AFtl,ABth,ABtl);
  k_embT<<<256,256>>>(nemb,EMBT);
  k_encoder<<<dim3(32,16,12),dim3(32,8)>>>(x,Wenc,benc,EMBT,XEh,XEl);
  k_packRUT<<<256,256>>>(Wr,Wu,br,bu,RUh,RUl,BRU);
  k_packT<<<256,256>>>(Wc,WCh,WCl,512);
  k_packT<<<160,256>>>(Wdiff,WDh,WDl,320);
  cudaMemsetAsync(Hf,0,(size_t)2*M1*4);   // Hf + H pairs

  // A^2 for both supports (A = pair, B = A^T hi)
  {
    Z4 z;
    z.Ah[0]=AFh; z.Al[0]=AFl; z.Bh[0]=AFth; z.Ch[0]=A2Fh; z.Cl[0]=A2Fl;
    z.Ah[1]=ABh; z.Al[1]=ABl; z.Bh[1]=ABth; z.Ch[1]=A2Bh; z.Cl[1]=A2Bl;
    z.Ah[2]=AFh; z.Al[2]=AFl; z.Bh[2]=AFth; z.Ch[2]=A2Fh; z.Cl[2]=A2Fl;
    z.Ah[3]=AFh; z.Al[3]=AFl; z.Bh[3]=AFth; z.Ch[3]=A2Fh; z.Cl[3]=A2Fl;
    hop_mma<<<dim3(8,8,2),256,SMEMB>>>(z);
  }
  // all x-hops for all t, all 4 supports, one launch
  {
    Z4 z;
    for(int s=0;s<4;s++){
      z.Ah[s]=XEh; z.Al[s]=XEl;
      z.Bh[s]=Sh[s];
      z.Ch[s]=BP(O_XHh+(size_t)s*6*M1);
      z.Cl[s]=BP(O_XHl+(size_t)s*6*M1);
    }
    hop_mma<<<dim3(8,96,4),256,SMEMB>>>(z);
  }

  Z4 zh, zt;
  for(int s=0;s<4;s++){
    zh.Ah[s]=Hh; zh.Al[s]=Hl; zh.Bh[s]=Sh[s];
    zh.Ch[s]=BP(O_HHh+(size_t)s*HK); zh.Cl[s]=BP(O_HHl+(size_t)s*HK);
    zt.Ah[s]=RHh; zt.Al[s]=RHl; zt.Bh[s]=Sh[s];
    zt.Ch[s]=BP(O_THh+(size_t)s*HK); zt.Cl[s]=BP(O_THl+(size_t)s*HK);
  }

  dim3 gHop(8,8,4), gGate(8,16);
  for(int t=0;t<12;t++){
    G8P gru,gcc;
    for(int s=0;s<4;s++){
      gru.h[2*s]=BP(O_XHh+(size_t)s*6*M1+(size_t)t*HK);
      gru.h[2*s+1]=BP(O_HHh+(size_t)s*HK);
      gcc.h[2*s]=gru.h[2*s];
      gcc.h[2*s+1]=BP(O_THh+(size_t)s*HK);
    }
    hop_mma<<<gHop,256,SMEMB>>>(zh);
    gate_mma<<<gGate,256,SMEMB>>>(512,16,0,RUh,RUl,gru,BRU,Hf,U,RHh,RHl,Hh,Hl,Z);
    hop_mma<<<gHop,256,SMEMB>>>(zt);
    gate_mma<<<gGate,256,SMEMB>>>(512,16,1,WCh,WCl,gcc,bc,Hf,U,RHh,RHl,Hh,Hl,Z);
  }

  // ---- DiffConv readout ----
  cudaMemsetAsync(WFf,0,(size_t)2*M1*4);
  cudaMemsetAsync(DGD,0,2048*4);
  k_deg<<<(E+255)/256,256>>>(src,dst,ew,DGD,DGD+1024,E);
  k_buildW<<<(E+255)/256,256>>>(src,dst,ew,DGD,DGD+1024,WFf,WFf+M1,E);
  k_cvt<<<4096,256>>>(WFf,WFh,WFl,(int)M1);
  k_cvt<<<4096,256>>>(WFf+M1,WBh,WBl,(int)M1);

  {
    Z4 z;
    z.Ah[0]=Hh; z.Al[0]=Hl; z.Bh[0]=WFh; z.Ch[0]=BP(O_D1Fh); z.Cl[0]=BP(O_D1Fl);
    z.Ah[1]=Hh; z.Al[1]=Hl; z.Bh[1]=WBh; z.Ch[1]=BP(O_D1Bh); z.Cl[1]=BP(O_D1Bl);
    z.Ah[2]=Hh; z.Al[2]=Hl; z.Bh[2]=WFh; z.Ch[2]=BP(O_D1Fh); z.Cl[2]=BP(O_D1Fl);
    z.Ah[3]=Hh; z.Al[3]=Hl; z.Bh[3]=WFh; z.Ch[3]=BP(O_D1Fh); z.Cl[3]=BP(O_D1Fl);
    hop_mma<<<dim3(8,8,2),256,SMEMB>>>(z);
    Z4 z2;
    z2.Ah[0]=BP(O_D1Fh); z2.Al[0]=BP(O_D1Fl); z2.Bh[0]=WFh;
    z2.Ch[0]=BP(O_D2Fh); z2.Cl[0]=BP(O_D2Fl);
    z2.Ah[1]=BP(O_D1Bh); z2.Al[1]=BP(O_D1Bl); z2.Bh[1]=WBh;
    z2.Ch[1]=BP(O_D2Bh); z2.Cl[1]=BP(O_D2Bl);
    z2.Ah[2]=z2.Ah[0]; z2.Al[2]=z2.Al[0]; z2.Bh[2]=WFh;
    z2.Ch[2]=z2.Ch[0]; z2.Cl[2]=z2.Cl[0];
    z2.Ah[3]=z2.Ah[0]; z2.Al[3]=z2.Al[0]; z2.Bh[3]=WFh;
    z2.Ch[3]=z2.Ch[0]; z2.Cl[3]=z2.Cl[0];
    hop_mma<<<dim3(8,8,2),256,SMEMB>>>(z2);
  }
  {
    G8P gd;
    gd.h[0]=Hh;
    gd.h[1]=BP(O_D1Fh);
    gd.h[2]=BP(O_D2Fh);
    gd.h[3]=BP(O_D1Bh);
    gd.h[4]=BP(O_D2Bh);
    gd.h[5]=Hh; gd.h[6]=Hh; gd.h[7]=Hh;
    gate_mma<<<gGate,256,SMEMB>>>(320,10,2,WDh,WDl,gd,bdiff,Hf,U,RHh,RHl,Hh,Hl,Z);
  }
  k_decoder<<<dim3(8,16),128>>>(Z,Wdec,bdec,out);
}

// round 15
// speedup vs baseline: 4.1505x; 1.1538x over previous
#include <cuda_runtime.h>
#include <cuda_fp16.h>
#include <math.h>
#include <stdint.h>

#define M1 ((size_t)1<<20)
#define HK ((size_t)1<<19)
constexpr size_t O_XEh=0, O_XEl=6*M1,
 O_XHh=12*M1, O_XHl=36*M1,
 O_HHh=60*M1, O_HHl=62*M1,
 O_THh=64*M1, O_THl=66*M1,
 O_Hf=68*M1, O_Hh=69*M1, O_Hl=69*M1+HK,
 O_RHh=70*M1, O_RHl=70*M1+HK,
 O_U=71*M1, O_Z=72*M1,
 O_D1Fh=73*M1, O_D1Fl=73*M1+HK, O_D1Bh=74*M1, O_D1Bl=74*M1+HK,
 O_D2Fh=75*M1, O_D2Fl=75*M1+HK, O_D2Bh=76*M1, O_D2Bl=76*M1+HK,
 O_WFf=77*M1,
 O_AFh=79*M1, O_AFl=79*M1+HK, O_A2Fh=80*M1, O_A2Fl=80*M1+HK,
 O_ABh=81*M1, O_ABl=81*M1+HK, O_A2Bh=82*M1, O_A2Bl=82*M1+HK,
 O_AFth=83*M1, O_AFtl=83*M1+HK, O_ABth=84*M1, O_ABtl=84*M1+HK,
 O_WFh=85*M1, O_WFl=85*M1+HK, O_WBh=86*M1, O_WBl=86*M1+HK,
 O_EMBT=87*M1,
 O_RUh=O_EMBT+65536, O_RUl=O_RUh+32768,
 O_WCh=O_RUl+32768, O_WCl=O_WCh+32768,
 O_WDh=O_WCl+32768, O_WDl=O_WDh+20480,
 O_BRU=O_WDl+20480, O_RS=O_BRU+128, O_CS=O_RS+1024, O_DGD=O_CS+1024,
 O_END=O_DGD+2048;
__device__ float g_buf[O_END];

// ---------- helpers ----------
__device__ __forceinline__ uint32_t s2u(const void*p){uint32_t a;asm("{ .reg .u64 t; cvta.to.shared.u64 t, %1; cvt.u32.u64 %0, t; }":"=r"(a):"l"(p));return a;}
__device__ __forceinline__ void sph(float x,__half&h,__half&l){h=__float2half(x);l=__float2half(x-__half2float(h));}
__device__ __forceinline__ uint32_t pkh(__half a,__half b){__half2 t;t.x=a;t.y=b;return *(uint32_t*)&t;}
__device__ __forceinline__ void ldsm4(uint32_t* r,uint32_t addr){
  asm volatile("ldmatrix.sync.aligned.m8n8.x4.shared.b16 {%0,%1,%2,%3}, [%4];"
   : "=r"(r[0]),"=r"(r[1]),"=r"(r[2]),"=r"(r[3]) : "r"(addr));
}
__device__ __forceinline__ void mmaf(float* c,const uint32_t* a,uint32_t b0,uint32_t b1){
  asm volatile("mma.sync.aligned.m16n8k16.row.col.f32.f16.f16.f32 "
    "{%0,%1,%2,%3}, {%4,%5,%6,%7}, {%8,%9}, {%0,%1,%2,%3};"
    : "+f"(c[0]),"+f"(c[1]),"+f"(c[2]),"+f"(c[3])
    : "r"(a[0]),"r"(a[1]),"r"(a[2]),"r"(a[3]),"r"(b0),"r"(b1));
}
__device__ __forceinline__ void cpa16(uint32_t dst,const void* src){
  asm volatile("cp.async.cg.shared.global [%0], [%1], 16;"::"r"(dst),"l"(src));
}
#define CP_COMMIT asm volatile("cp.async.commit_group;":::"memory")
#define CP_WAIT0  asm volatile("cp.async.wait_group 0;":::"memory")
__device__ __forceinline__ uint32_t toff(int r,int kbyte){return r*64 + (kbyte ^ ((r&3)<<4));}
__device__ __forceinline__ float sgm(float x){return 1.f/(1.f+expf(-x));}
#define CHB 24576
#define SMEMB 49152

// per-warp compute of one K=32 chunk, 2-term: (Ah+Al)*Bh
__device__ __forceinline__ void compute_chunk(uint32_t sbase,float c[2][8][4],
                                              int wm,int wn,int lane){
  const int ar=(lane&15), acs=((lane>>4)<<4);
  const int lr=lane&7, sel=lane>>3;
  const int brb=wn*64+((sel>>1)<<3)+lr, bcs=(sel&1)<<4;
#pragma unroll
  for(int s=0;s<2;s++){
    uint32_t a[2][2][4], b[4][4];
#pragma unroll
    for(int mt=0;mt<2;mt++){
      int r=wm*32+mt*16+ar;
      uint32_t off=toff(r,s*32+acs);
      ldsm4(a[mt][0],sbase+off);
      ldsm4(a[mt][1],sbase+8192+off);
    }
#pragma unroll
    for(int g=0;g<4;g++){
      int r=brb+g*16;
      ldsm4(b[g],sbase+16384+toff(r,s*32+bcs));
    }
#pragma unroll
    for(int mt=0;mt<2;mt++)
#pragma unroll
      for(int g=0;g<4;g++){
        mmaf(c[mt][2*g],  a[mt][0],b[g][0],b[g][1]);
        mmaf(c[mt][2*g],  a[mt][1],b[g][0],b[g][1]);
        mmaf(c[mt][2*g+1],a[mt][0],b[g][2],b[g][3]);
        mmaf(c[mt][2*g+1],a[mt][1],b[g][2],b[g][3]);
      }
  }
}

// ---------- hop GEMM: cp.async prefetch, occupancy 2 ----------
struct Z4 {
  const __half *Ah[4],*Al[4],*Bh[4];
  __half *Ch[4],*Cl[4];
};
__global__ void __launch_bounds__(256,2) hop_mma(Z4 z)
{
  extern __shared__ char smem[];
  const int bz=blockIdx.z;
  const __half* Ah=z.Ah[bz]; const __half* Al=z.Al[bz];
  const __half* Bh=z.Bh[bz];
  __half* Ch=z.Ch[bz]; __half* Cl=z.Cl[bz];
  const int tid=threadIdx.x, lane=tid&31, warp=tid>>5, wm=warp&3, wn=warp>>2;
  const int bm=blockIdx.y*128, bn=blockIdx.x*128;
  uint32_t sb=s2u(smem);

  float c[2][8][4];
#pragma unroll
  for(int i=0;i<2;i++)
#pragma unroll
    for(int j=0;j<8;j++){c[i][j][0]=0;c[i][j][1]=0;c[i][j][2]=0;c[i][j][3]=0;}

  const __half* aptr[4]; uint32_t soA[4];
  const __half* bptr[2]; uint32_t soB[2];
#pragma unroll
  for(int j=0;j<4;j++){
    int idx=tid+j*256, mm=idx>>9, id2=idx&511, r=id2>>2, c16=id2&3;
    aptr[j]=(mm?Al:Ah)+(size_t)(bm+r)*1024+c16*8;
    soA[j]=mm*8192+toff(r,c16*16);
  }
#pragma unroll
  for(int j=0;j<2;j++){
    int idx=tid+j*256, r=idx>>2, c16=idx&3;
    bptr[j]=Bh+(size_t)(bn+r)*1024+c16*8;
    soB[j]=16384+toff(r,c16*16);
  }
  // prologue: chunk 0
#pragma unroll
  for(int j=0;j<4;j++) cpa16(sb+soA[j],aptr[j]);
#pragma unroll
  for(int j=0;j<2;j++) cpa16(sb+soB[j],bptr[j]);
  CP_COMMIT;
  CP_WAIT0;
  __syncthreads();

  for(int kc=0;kc<32;kc++){
    int cur=kc&1;
    if(kc<31){
      int k0=(kc+1)<<5;
      uint32_t nb=sb+(cur^1)*CHB;
#pragma unroll
      for(int j=0;j<4;j++) cpa16(nb+soA[j],aptr[j]+k0);
#pragma unroll
      for(int j=0;j<2;j++) cpa16(nb+soB[j],bptr[j]+k0);
      CP_COMMIT;
    }
    compute_chunk(sb+cur*CHB,c,wm,wn,lane);
    if(kc<31) CP_WAIT0;
    __syncthreads();
  }

#pragma unroll
  for(int mt=0;mt<2;mt++){
#pragma unroll
    for(int half=0;half<2;half++){
      int gm=bm+wm*32+mt*16+(lane>>2)+half*8;
      size_t rowoff=(size_t)gm*1024+bn+wn*64+(lane&3)*2;
#pragma unroll
      for(int f=0;f<8;f++){
        float v0=c[mt][f][half*2], v1=c[mt][f][half*2+1];
        __half h0,l0,h1,l1; sph(v0,h0,l0); sph(v1,h1,l1);
        *(uint32_t*)(Ch+rowoff+f*8)=pkh(h0,h1);
        *(uint32_t*)(Cl+rowoff+f*8)=pkh(l0,l1);
      }
    }
  }
}

// ---------- gate GEMM with fused epilogues (occ 1, transposing loader) ----------
struct G8P{ const __half* h[8]; };
__global__ void __launch_bounds__(256,1) gate_mma(
    int Ktot,int NC,int mode,
    const __half* Wh,const __half* Wl,
    G8P g,const float* bias,
    float* Hf,float* U,
    __half* RHh,__half* RHl,
    __half* Hh,__half* Hl,
    float* Z)
{
  extern __shared__ char smem[];
  const int tid=threadIdx.x, lane=tid&31, warp=tid>>5, wm=warp&3, wn=warp>>2;
  const int bn=blockIdx.x*128, b=blockIdx.y;
  uint32_t sb=s2u(smem);

  float c[2][8][4];
#pragma unroll
  for(int i=0;i<2;i++)
#pragma unroll
    for(int j=0;j<8;j++){c[i][j][0]=0;c[i][j][1]=0;c[i][j][2]=0;c[i][j][3]=0;}

  const __half* wptr[4]; uint32_t soW[4];
#pragma unroll
  for(int j=0;j<4;j++){
    int idx=tid+j*256, mm=idx>>9, id2=idx&511, r=id2>>2, c16=id2&3;
    wptr[j]=(mm?Wl:Wh)+(size_t)r*Ktot+c16*8;
    soW[j]=mm*8192+toff(r,c16*16);
  }
  {
    const __half* srch=g.h[0]+(size_t)b*65536;
#pragma unroll
    for(int j=0;j<4;j++) cpa16(sb+soW[j],wptr[j]);
    CP_COMMIT;
#pragma unroll
    for(int j=0;j<4;j++){
      int idx=tid+j*256, kk=idx>>5, v4=idx&31;
      uint2 vh=*(const uint2*)(srch+(size_t)kk*1024+bn+v4*4);
      int r0=v4*4;
      *(uint16_t*)(smem+16384+toff(r0  ,kk*2))=(uint16_t)(vh.x);
      *(uint16_t*)(smem+16384+toff(r0+1,kk*2))=(uint16_t)(vh.x>>16);
      *(uint16_t*)(smem+16384+toff(r0+2,kk*2))=(uint16_t)(vh.y);
      *(uint16_t*)(smem+16384+toff(r0+3,kk*2))=(uint16_t)(vh.y>>16);
    }
    CP_WAIT0;
  }
  __syncthreads();

  for(int kc=0;kc<NC;kc++){
    int cur=kc&1;
    uint2 vh[4];
    if(kc+1<NC){
      int kn=kc+1, k0=kn<<5;
      const __half* srch=g.h[kn>>1]+(size_t)(kn&1)*32768+(size_t)b*65536;
      uint32_t nb=sb+(cur^1)*CHB;
#pragma unroll
      for(int j=0;j<4;j++) cpa16(nb+soW[j],wptr[j]+k0);
      CP_COMMIT;
#pragma unroll
      for(int j=0;j<4;j++){
        int idx=tid+j*256, kk=idx>>5, v4=idx&31;
        vh[j]=*(const uint2*)(srch+(size_t)kk*1024+bn+v4*4);
      }
    }
    compute_chunk(sb+cur*CHB,c,wm,wn,lane);
    if(kc+1<NC){
      char* nb=smem+(cur^1)*CHB;
#pragma unroll
      for(int j=0;j<4;j++){
        int idx=tid+j*256, kk=idx>>5, v4=idx&31;
        int r0=v4*4;
        *(uint16_t*)(nb+16384+toff(r0  ,kk*2))=(uint16_t)(vh[j].x);
        *(uint16_t*)(nb+16384+toff(r0+1,kk*2))=(uint16_t)(vh[j].x>>16);
        *(uint16_t*)(nb+16384+toff(r0+2,kk*2))=(uint16_t)(vh[j].y);
        *(uint16_t*)(nb+16384+toff(r0+3,kk*2))=(uint16_t)(vh[j].y>>16);
      }
      CP_WAIT0;
    }
    __syncthreads();
  }

#pragma unroll
  for(int mt=0;mt<2;mt++){
#pragma unroll
    for(int half=0;half<2;half++){
      int m=wm*32+mt*16+(lane>>2)+half*8;
      int col=bn+wn*64+(lane&3)*2;
      if(mode==0){
        float bv=bias[m];
        if(m<64){
          size_t ro=(size_t)(b*64+m)*1024+col;
#pragma unroll
          for(int f=0;f<8;f++){
            float2 hv=*(const float2*)(Hf+ro+f*8);
            float r0=sgm(c[mt][f][half*2]+bv), r1=sgm(c[mt][f][half*2+1]+bv);
            float x0=r0*hv.x, x1=r1*hv.y;
            __half h0,l0,h1,l1; sph(x0,h0,l0); sph(x1,h1,l1);
            *(uint32_t*)(RHh+ro+f*8)=pkh(h0,h1);
            *(uint32_t*)(RHl+ro+f*8)=pkh(l0,l1);
          }
        } else {
          size_t ro=(size_t)(b*64+(m-64))*1024+col;
#pragma unroll
          for(int f=0;f<8;f++){
            float2 v; v.x=sgm(c[mt][f][half*2]+bv); v.y=sgm(c[mt][f][half*2+1]+bv);
            *(float2*)(U+ro+f*8)=v;
          }
        }
      } else if(mode==1){
        if(m<64){
          float bv=bias[m];
          size_t ro=(size_t)(b*64+m)*1024+col;
#pragma unroll
          for(int f=0;f<8;f++){
            float2 uu=*(const float2*)(U+ro+f*8);
            float2 hh=*(const float2*)(Hf+ro+f*8);
            float c0=tanhf(c[mt][f][half*2]+bv), c1=tanhf(c[mt][f][half*2+1]+bv);
            float n0=uu.x*hh.x+(1.f-uu.x)*c0;
            float n1=uu.y*hh.y+(1.f-uu.y)*c1;
            float2 v; v.x=n0; v.y=n1;
            *(float2*)(Hf+ro+f*8)=v;
            __half h0,l0,h1,l1; sph(n0,h0,l0); sph(n1,h1,l1);
            *(uint32_t*)(Hh+ro+f*8)=pkh(h0,h1);
            *(uint32_t*)(Hl+ro+f*8)=pkh(l0,l1);
          }
        }
      } else {
        if(m<64){
          float bv=bias[m];
          size_t ro=(size_t)(b*64+m)*1024+col;
#pragma unroll
          for(int f=0;f<8;f++){
            float2 v; v.x=c[mt][f][half*2]+bv; v.y=c[mt][f][half*2+1]+bv;
            *(float2*)(Z+ro+f*8)=v;
          }
        }
      }
    }
  }
}

// ---------- small kernels ----------
__global__ void k_normprep(const float* adj,float* rs,float* cs){
  int i=blockIdx.x,t=threadIdx.x; float r=0,c=0;
  for(int j=t;j<1024;j+=256){r+=adj[(size_t)i*1024+j];c+=adj[(size_t)j*1024+i];}
  __shared__ float sr[256],sc[256]; sr[t]=r;sc[t]=c;__syncthreads();
  for(int s=128;s>0;s>>=1){if(t<s){sr[t]+=sr[t+s];sc[t]+=sc[t+s];}__syncthreads();}
  if(t==0){rs[i]=sr[0];cs[i]=sc[0];}
}
__global__ void k_norm_cvt(const float* adj,const float* rs,const float* cs,
    __half* AFh,__half* AFl,__half* ABh,__half* ABl,
    __half* AFth,__half* AFtl,__half* ABth,__half* ABtl){
  size_t i=(size_t)blockIdx.x*256+threadIdx.x;
  int w=(int)(i>>10),v=(int)(i&1023);
  size_t ti=(size_t)v*1024+w;
  __half h,l;
  sph(adj[i]/rs[w],h,l); AFh[i]=h; AFl[i]=l; AFth[ti]=h; AFtl[ti]=l;
  sph(adj[ti]/cs[w],h,l); ABh[i]=h; ABl[i]=l; ABth[ti]=h; ABtl[ti]=l;
}
__global__ void k_cvt(const float* s,__half* h,__half* l,int n){
  int i=blockIdx.x*256+threadIdx.x;
  if(i<n){__half hh,ll;sph(s[i],hh,ll);h[i]=hh;l[i]=ll;}
}
__global__ void k_embT(const float* emb,float* et){
  int i=blockIdx.x*256+threadIdx.x;
  et[i]=emb[(size_t)(i&1023)*64+(i>>10)];
}
__global__ void k_encoder(const float* x,const float* We,const float* be,
                          const float* embT,__half* XEh,__half* XEl){
  int t=blockIdx.z,b=blockIdx.y,v0=blockIdx.x*32;
  __shared__ float xv[32][8];
  int tid=threadIdx.y*32+threadIdx.x;
  xv[tid>>3][tid&7]=x[(((size_t)b*12+t)*1024+v0)*8+tid];
  __syncthreads();
  int tx=threadIdx.x;
  for(int hh=0;hh<8;hh++){
    int h=threadIdx.y*8+hh;
    float s=be[h]+embT[(size_t)h*1024+v0+tx];
#pragma unroll
    for(int f=0;f<8;f++) s+=xv[tx][f]*We[f*64+h];
    __half bh,bl; sph(s,bh,bl);
    size_t o=(size_t)t*M1+(size_t)(b*64+h)*1024+v0+tx;
    XEh[o]=bh; XEl[o]=bl;
  }
}
__global__ void k_packRUT(const float* Wr,const float* Wu,const float* br,const float* bu,
    __half* Wh,__half* Wl,float* bru){
  int i=blockIdx.x*256+threadIdx.x;
  if(i<65536){int j=i>>9,k=i&511;
    float w=(j<64)?Wr[k*64+j]:Wu[k*64+j-64];
    __half h,l;sph(w,h,l);Wh[i]=h;Wl[i]=l;}
  if(i<128) bru[i]=(i<64)?br[i]:bu[i-64];
}
__global__ void k_packT(const float* W,__half* Wh,__half* Wl,int Kd){
  int i=blockIdx.x*256+threadIdx.x;
  if(i<128*Kd){int j=i/Kd,k=i-j*Kd;
    float w=(j<64)?W[k*64+j]:0.f;
    __half h,l;sph(w,h,l);Wh[i]=h;Wl[i]=l;}
}
__global__ void k_deg(const int* src,const int* dst,const float* w,
                      float* dd,float* ds,int E){
  int e=blockIdx.x*256+threadIdx.x;
  if(e<E){atomicAdd(&dd[dst[e]],w[e]);atomicAdd(&ds[src[e]],w[e]);}
}
__global__ void k_buildW(const int* src,const int* dst,const float* w,
    const float* dd,const float* ds,float* Wf,float* Wb,int E){
  int e=blockIdx.x*256+threadIdx.x;
  if(e<E){int s=src[e],d=dst[e];float we=w[e];
    float a=dd[d],b2=ds[s];
    atomicAdd(&Wf[(size_t)d*1024+s],(a>0.f)?we/a:0.f);
    atomicAdd(&Wb[(size_t)s*1024+d],(b2>0.f)?we/b2:0.f);}
}
__global__ void k_decoder(const float* Z,const float* Wd,const float* bd,float* out){
  int bn=blockIdx.x*128,b=blockIdx.y,tx=threadIdx.x;
  __shared__ float Ws[64*96],bs[96];
  for(int i=tx;i<6144;i+=128) Ws[i]=Wd[i];
  if(tx<96) bs[tx]=bd[tx];
  __syncthreads();
  int v=bn+tx;
  float z[64];
#pragma unroll
  for(int h=0;h<64;h++) z[h]=Z[(size_t)(b*64+h)*1024+v];
  for(int j=0;j<96;j++){
    float s=bs[j];
#pragma unroll
    for(int h=0;h<64;h++) s+=z[h]*Ws[h*96+j];
    out[(((size_t)b*12+(j>>3))*1024+v)*8+(j&7)]=s;
  }
}

// ---------- driver ----------
extern "C" void kernel_launch(void* const* d_in,const int* in_sizes,int n_in,
                              void* d_out,int out_size){
  const float* x=(const float*)d_in[0];
  const int* ei=(const int*)d_in[1];
  const float* ew=(const float*)d_in[2];
  const float* adj=(const float*)d_in[3];
  const float* Wenc=(const float*)d_in[4];
  const float* benc=(const float*)d_in[5];
  const float* nemb=(const float*)d_in[6];
  const float* Wr=(const float*)d_in[7];  const float* br=(const float*)d_in[8];
  const float* Wu=(const float*)d_in[9];  const float* bu=(const float*)d_in[10];
  const float* Wc=(const float*)d_in[11]; const float* bc=(const float*)d_in[12];
  const float* Wdiff=(const float*)d_in[13]; const float* bdiff=(const float*)d_in[14];
  const float* Wdec=(const float*)d_in[15];  const float* bdec=(const float*)d_in[16];
  float* out=(float*)d_out;
  const int E=in_sizes[2];
  const int* src=ei; const int* dst=ei+E;

  float* B=nullptr; cudaGetSymbolAddress((void**)&B,g_buf);
#define BP(o) ((__half*)(B+(o)))
  float *Hf=B+O_Hf,*U=B+O_U,*Z=B+O_Z,*WFf=B+O_WFf,*EMBT=B+O_EMBT,
        *BRU=B+O_BRU,*RS=B+O_RS,*CS=B+O_CS,*DGD=B+O_DGD;
  __half *XEh=BP(O_XEh),*XEl=BP(O_XEl),
   *Hh=BP(O_Hh),*Hl=BP(O_Hl),*RHh=BP(O_RHh),*RHl=BP(O_RHl),
   *AFh=BP(O_AFh),*AFl=BP(O_AFl),*A2Fh=BP(O_A2Fh),*A2Fl=BP(O_A2Fl),
   *ABh=BP(O_ABh),*ABl=BP(O_ABl),*A2Bh=BP(O_A2Bh),*A2Bl=BP(O_A2Bl),
   *AFth=BP(O_AFth),*AFtl=BP(O_AFtl),*ABth=BP(O_ABth),*ABtl=BP(O_ABtl),
   *WFh=BP(O_WFh),*WFl=BP(O_WFl),*WBh=BP(O_WBh),*WBl=BP(O_WBl),
   *RUh=BP(O_RUh),*RUl=BP(O_RUl),*WCh=BP(O_WCh),*WCl=BP(O_WCl),
   *WDh=BP(O_WDh),*WDl=BP(O_WDl);
  const __half* Sh[4]={AFh,A2Fh,ABh,A2Bh};

  cudaFuncSetAttribute(hop_mma,cudaFuncAttributeMaxDynamicSharedMemorySize,SMEMB);
  cudaFuncSetAttribute(gate_mma,cudaFuncAttributeMaxDynamicSharedMemorySize,SMEMB);

  k_normprep<<<1024,256>>>(adj,RS,CS);
  k_norm_cvt<<<4096,256>>>(adj,RS,CS,AFh,AFl,ABh,ABl,AFth,AFtl,ABth,ABtl);
  k_embT<<<256,256>>>(nemb,EMBT);
  k_encoder<<<dim3(32,16,12),dim3(32,8)>>>(x,Wenc,benc,EMBT,XEh,XEl);
  k_packRUT<<<256,256>>>(Wr,Wu,br,bu,RUh,RUl,BRU);
  k_packT<<<256,256>>>(Wc,WCh,WCl,512);
  k_packT<<<160,256>>>(Wdiff,WDh,WDl,320);
  cudaMemsetAsync(Hf,0,(size_t)2*M1*4);

  // A^2 for both supports
  {
    Z4 z;
    z.Ah[0]=AFh; z.Al[0]=AFl; z.Bh[0]=AFth; z.Ch[0]=A2Fh; z.Cl[0]=A2Fl;
    z.Ah[1]=ABh; z.Al[1]=ABl; z.Bh[1]=ABth; z.Ch[1]=A2Bh; z.Cl[1]=A2Bl;
    z.Ah[2]=AFh; z.Al[2]=AFl; z.Bh[2]=AFth; z.Ch[2]=A2Fh; z.Cl[2]=A2Fl;
    z.Ah[3]=AFh; z.Al[3]=AFl; z.Bh[3]=AFth; z.Ch[3]=A2Fh; z.Cl[3]=A2Fl;
    hop_mma<<<dim3(8,8,2),256,SMEMB>>>(z);
  }
  // all x-hops, one launch
  {
    Z4 z;
    for(int s=0;s<4;s++){
      z.Ah[s]=XEh; z.Al[s]=XEl;
      z.Bh[s]=Sh[s];
      z.Ch[s]=BP(O_XHh+(size_t)s*6*M1);
      z.Cl[s]=BP(O_XHl+(size_t)s*6*M1);
    }
    hop_mma<<<dim3(8,96,4),256,SMEMB>>>(z);
  }

  Z4 zh, zt;
  for(int s=0;s<4;s++){
    zh.Ah[s]=Hh; zh.Al[s]=Hl; zh.Bh[s]=Sh[s];
    zh.Ch[s]=BP(O_HHh+(size_t)s*HK); zh.Cl[s]=BP(O_HHl+(size_t)s*HK);
    zt.Ah[s]=RHh; zt.Al[s]=RHl; zt.Bh[s]=Sh[s];
    zt.Ch[s]=BP(O_THh+(size_t)s*HK); zt.Cl[s]=BP(O_THl+(size_t)s*HK);
  }

  dim3 gHop(8,8,4), gGate(8,16);
  for(int t=0;t<12;t++){
    G8P gru,gcc;
    for(int s=0;s<4;s++){
      gru.h[2*s]=BP(O_XHh+(size_t)s*6*M1+(size_t)t*HK);
      gru.h[2*s+1]=BP(O_HHh+(size_t)s*HK);
      gcc.h[2*s]=gru.h[2*s];
      gcc.h[2*s+1]=BP(O_THh+(size_t)s*HK);
    }
    hop_mma<<<gHop,256,SMEMB>>>(zh);
    gate_mma<<<gGate,256,SMEMB>>>(512,16,0,RUh,RUl,gru,BRU,Hf,U,RHh,RHl,Hh,Hl,Z);
    hop_mma<<<gHop,256,SMEMB>>>(zt);
    gate_mma<<<gGate,256,SMEMB>>>(512,16,1,WCh,WCl,gcc,bc,Hf,U,RHh,RHl,Hh,Hl,Z);
  }

  // ---- DiffConv readout ----
  cudaMemsetAsync(WFf,0,(size_t)2*M1*4);
  cudaMemsetAsync(DGD,0,2048*4);
  k_deg<<<(E+255)/256,256>>>(src,dst,ew,DGD,DGD+1024,E);
  k_buildW<<<(E+255)/256,256>>>(src,dst,ew,DGD,DGD+1024,WFf,WFf+M1,E);
  k_cvt<<<4096,256>>>(WFf,WFh,WFl,(int)M1);
  k_cvt<<<4096,256>>>(WFf+M1,WBh,WBl,(int)M1);

  {
    Z4 z;
    z.Ah[0]=Hh; z.Al[0]=Hl; z.Bh[0]=WFh; z.Ch[0]=BP(O_D1Fh); z.Cl[0]=BP(O_D1Fl);
    z.Ah[1]=Hh; z.Al[1]=Hl; z.Bh[1]=WBh; z.Ch[1]=BP(O_D1Bh); z.Cl[1]=BP(O_D1Bl);
    z.Ah[2]=Hh; z.Al[2]=Hl; z.Bh[2]=WFh; z.Ch[2]=BP(O_D1Fh); z.Cl[2]=BP(O_D1Fl);
    z.Ah[3]=Hh; z.Al[3]=Hl; z.Bh[3]=WFh; z.Ch[3]=BP(O_D1Fh); z.Cl[3]=BP(O_D1Fl);
    hop_mma<<<dim3(8,8,2),256,SMEMB>>>(z);
    Z4 z2;
    z2.Ah[0]=BP(O_D1Fh); z2.Al[0]=BP(O_D1Fl); z2.Bh[0]=WFh;
    z2.Ch[0]=BP(O_D2Fh); z2.Cl[0]=BP(O_D2Fl);
    z2.Ah[1]=BP(O_D1Bh); z2.Al[1]=BP(O_D1Bl); z2.Bh[1]=WBh;
    z2.Ch[1]=BP(O_D2Bh); z2.Cl[1]=BP(O_D2Bl);
    z2.Ah[2]=z2.Ah[0]; z2.Al[2]=z2.Al[0]; z2.Bh[2]=WFh;
    z2.Ch[2]=z2.Ch[0]; z2.Cl[2]=z2.Cl[0];
    z2.Ah[3]=z2.Ah[0]; z2.Al[3]=z2.Al[0]; z2.Bh[3]=WFh;
    z2.Ch[3]=z2.Ch[0]; z2.Cl[3]=z2.Cl[0];
    hop_mma<<<dim3(8,8,2),256,SMEMB>>>(z2);
  }
  {
    G8P gd;
    gd.h[0]=Hh;
    gd.h[1]=BP(O_D1Fh);
    gd.h[2]=BP(O_D2Fh);
    gd.h[3]=BP(O_D1Bh);
    gd.h[4]=BP(O_D2Bh);
    gd.h[5]=Hh; gd.h[6]=Hh; gd.h[7]=Hh;
    gate_mma<<<gGate,256,SMEMB>>>(320,10,2,WDh,WDl,gd,bdiff,Hf,U,RHh,RHl,Hh,Hl,Z);
  }
  k_decoder<<<dim3(8,16),128>>>(Z,Wdec,bdec,out);
}